// round 2
// baseline (speedup 1.0000x reference)
#include <cuda_runtime.h>
#include <cuda_bf16.h>

// FAVOR+ linear attention, fp32 SIMT tile kernels.
// B=8, Q=K=8192, D=DV=m=128 (dims derived from in_sizes where possible).
//
// Pipeline:
//   init_kernel : zero g_kv/g_ksum scratch
//   kv_kernel   : ks' = phi(ks*c) masked; g_kv += ks'^T @ vs; g_ksum += sum ks'
//   out_kernel  : qs' = phi(qs*c); out = (qs' @ g_kv) / max(qs'.g_ksum, EPS)

#define TILE 128
#define LD   132                 // smem leading dim (floats), 16B-aligned, conflict-tamed
#define ROWF (128 * LD)          // floats per 128x128 padded tile

static constexpr float NORMALIZER = 0.29730177875068026f;  // 128^-0.25
static constexpr float RSQRT_M    = 0.08838834764831845f;  // 1/sqrt(128)
static constexpr float EPS_DEN    = 1e-6f;

#define MAX_B 8
__device__ float g_kv[MAX_B * 128 * 128];
__device__ float g_ksum[MAX_B * 128];

// ---------------------------------------------------------------------------
// valid_lens may arrive as int32 (JAX x64-off canonicalization) or int64.
// Detect: int64 little-endian => odd 32-bit words are 0 and even words in range.
// All detection reads are within the first 32 bytes (safe for both layouts).
// ---------------------------------------------------------------------------
__device__ __forceinline__ int get_vl(const void* p, int b, int K) {
    const int* pi = (const int*)p;
    bool is64 = (pi[1] == 0) && (pi[3] == 0) && (pi[5] == 0) && (pi[7] == 0) &&
                (pi[0] >= 0 && pi[0] <= K) && (pi[2] >= 0 && pi[2] <= K) &&
                (pi[4] >= 0 && pi[4] <= K) && (pi[6] >= 0 && pi[6] <= K);
    return is64 ? pi[2 * b] : pi[b];
}

// ---------------------------------------------------------------------------
// Load a 128x128 fp32 tile (row-major, row stride 128) into smem TRANSPOSED:
// s[d*LD + row] = g[row*128 + d] * scale.  256 threads.
// Lane map: 8 rows x 4 float4 per warp-iter -> full 32B-sector efficiency on
// global reads, <=2-way conflicts on the scattered STS.
// ---------------------------------------------------------------------------
__device__ __forceinline__ void load_tile_T(const float* __restrict__ g,
                                            float* __restrict__ s, float scale) {
    int lane = threadIdx.x & 31;
    int warp = threadIdx.x >> 5;      // 0..7
    int row0 = lane >> 2;             // 0..7
    int d4l  = lane & 3;              // 0..3
#pragma unroll
    for (int t = 0; t < 16; t++) {
        int tt  = t * 8 + warp;       // 0..127
        int rg  = tt & 15;            // row group 0..15
        int dg  = tt >> 4;            // d4 group 0..7
        int row = rg * 8 + row0;
        int d4  = dg * 4 + d4l;
        float4 v = *(const float4*)(g + row * 128 + d4 * 4);
        s[(d4 * 4 + 0) * LD + row] = v.x * scale;
        s[(d4 * 4 + 1) * LD + row] = v.y * scale;
        s[(d4 * 4 + 2) * LD + row] = v.z * scale;
        s[(d4 * 4 + 3) * LD + row] = v.w * scale;
    }
}

// Row-major copy of a 128x128 fp32 tile into padded smem (for V / KV tiles).
__device__ __forceinline__ void load_tile_RM(const float* __restrict__ g,
                                             float* __restrict__ s) {
    int tid = threadIdx.x;
#pragma unroll
    for (int t = 0; t < 16; t++) {
        int idx = t * 256 + tid;      // 0..4095 float4 slots
        int row = idx >> 5;
        int d4  = idx & 31;
        float4 v = *(const float4*)(g + row * 128 + d4 * 4);
        *(float4*)(s + row * LD + d4 * 4) = v;
    }
}

// ---------------------------------------------------------------------------
// 128x128x128 register-tiled GEMM, both operands k-major in smem:
// acc[r][c] += sum_d A[d*LD + i0+r] * B[d*LD + j0+c]
// Thread grid 16x16, 8x8 fragments. a-reads: 2 float4 (2 addrs/warp,
// broadcast); b-reads: 2 float4 (4-phase inherent). FFMA-issue-bound.
// ---------------------------------------------------------------------------
__device__ __forceinline__ void gemm128(const float* __restrict__ A,
                                        const float* __restrict__ B,
                                        float acc[8][8], int i0, int j0) {
#pragma unroll 4
    for (int d = 0; d < 128; d++) {
        float4 a0 = *(const float4*)(A + d * LD + i0);
        float4 a1 = *(const float4*)(A + d * LD + i0 + 4);
        float4 b0 = *(const float4*)(B + d * LD + j0);
        float4 b1 = *(const float4*)(B + d * LD + j0 + 4);
        float av[8] = {a0.x, a0.y, a0.z, a0.w, a1.x, a1.y, a1.z, a1.w};
        float bv[8] = {b0.x, b0.y, b0.z, b0.w, b1.x, b1.y, b1.z, b1.w};
#pragma unroll
        for (int r = 0; r < 8; r++)
#pragma unroll
            for (int c = 0; c < 8; c++)
                acc[r][c] += av[r] * bv[c];
    }
}

// ---------------------------------------------------------------------------
__global__ void init_kernel(int b_count) {
    int i = blockIdx.x * blockDim.x + threadIdx.x;
    int n_kv = b_count * 128 * 128;
    if (i < n_kv) g_kv[i] = 0.0f;
    if (i < b_count * 128) g_ksum[i] = 0.0f;
}

// ---------------------------------------------------------------------------
// kv_kernel: grid (K/128, B), 256 threads.
// ---------------------------------------------------------------------------
__global__ void __launch_bounds__(256, 1)
kv_kernel(const float* __restrict__ ks, const float* __restrict__ vs,
          const float* __restrict__ proj, const void* __restrict__ vl,
          int K) {
    extern __shared__ float sm[];
    float* projT = sm;                 // [d][m]  (proj transposed)
    float* XT    = sm + ROWF;          // [d][k]  then reused as V [k][v]
    float* S     = sm + 2 * ROWF;      // [k][m]
    float* hbuf  = sm + 3 * ROWF;      // [128]

    int b  = blockIdx.y;
    int k0 = blockIdx.x * TILE;
    int tid = threadIdx.x;
    int tx = tid & 15, ty = tid >> 4;

    const float* ks_tile = ks + ((long)b * K + k0) * 128;
    const float* vs_tile = vs + ((long)b * K + k0) * 128;

    load_tile_T(proj, projT, 1.0f);
    load_tile_T(ks_tile, XT, NORMALIZER);
    __syncthreads();

    // h[i] = 0.5 * ||x_i||^2 (scaled x). Column reads: lanes hit consecutive
    // banks -> conflict-free.
    if (tid < 128) {
        float h = 0.0f;
#pragma unroll 8
        for (int d = 0; d < 128; d++) {
            float x = XT[d * LD + tid];
            h += x * x;
        }
        hbuf[tid] = 0.5f * h;
    }
    __syncthreads();

    // P = Xc @ proj^T  (output [k][m])
    float p[8][8];
#pragma unroll
    for (int r = 0; r < 8; r++)
#pragma unroll
        for (int c = 0; c < 8; c++) p[r][c] = 0.0f;
    gemm128(XT, projT, p, ty * 8, tx * 8);

    int vlb = get_vl(vl, b, K);

    // S = exp(P - h) * rsqrt(m), masked rows zeroed. float4 row-major writes.
#pragma unroll
    for (int r = 0; r < 8; r++) {
        int krow = ty * 8 + r;
        float hr = hbuf[krow];
        float rowscale = ((k0 + krow) < vlb) ? RSQRT_M : 0.0f;
        float4 o0, o1;
        o0.x = __expf(p[r][0] - hr) * rowscale;
        o0.y = __expf(p[r][1] - hr) * rowscale;
        o0.z = __expf(p[r][2] - hr) * rowscale;
        o0.w = __expf(p[r][3] - hr) * rowscale;
        o1.x = __expf(p[r][4] - hr) * rowscale;
        o1.y = __expf(p[r][5] - hr) * rowscale;
        o1.z = __expf(p[r][6] - hr) * rowscale;
        o1.w = __expf(p[r][7] - hr) * rowscale;
        *(float4*)(S + krow * LD + tx * 8)     = o0;
        *(float4*)(S + krow * LD + tx * 8 + 4) = o1;
    }
    __syncthreads();   // S ready; XT (ks) reads complete

    // V tile into XT buffer; ksum column-sums of S in parallel.
    load_tile_RM(vs_tile, XT);
    if (tid < 128) {
        float ssum = 0.0f;
#pragma unroll 8
        for (int k = 0; k < 128; k++) ssum += S[k * LD + tid];
        atomicAdd(&g_ksum[b * 128 + tid], ssum);
    }
    __syncthreads();

    // kv[m][v] += sum_k S[k][m] * V[k][v]
    float acc[8][8];
#pragma unroll
    for (int r = 0; r < 8; r++)
#pragma unroll
        for (int c = 0; c < 8; c++) acc[r][c] = 0.0f;
    gemm128(S, XT, acc, ty * 8, tx * 8);

    float* kvb = g_kv + b * 128 * 128;
#pragma unroll
    for (int r = 0; r < 8; r++)
#pragma unroll
        for (int c = 0; c < 8; c++)
            atomicAdd(&kvb[(ty * 8 + r) * 128 + tx * 8 + c], acc[r][c]);
}

// ---------------------------------------------------------------------------
// out_kernel: grid (Q/128, B), 256 threads.
// Computes S^T directly (operand swap) so no conflicted transpose store.
// ---------------------------------------------------------------------------
__global__ void __launch_bounds__(256, 1)
out_kernel(const float* __restrict__ qs, const float* __restrict__ proj,
           float* __restrict__ out, int Q) {
    extern __shared__ float sm[];
    float* projT  = sm;                 // [d][m], reused as KV [m][v]
    float* XT     = sm + ROWF;          // [d][q]
    float* ST     = sm + 2 * ROWF;      // [m][q]
    float* hbuf   = sm + 3 * ROWF;      // [128] per-q h
    float* denb   = sm + 3 * ROWF + 128;
    float* ksum_s = sm + 3 * ROWF + 256;

    int b  = blockIdx.y;
    int q0 = blockIdx.x * TILE;
    int tid = threadIdx.x;
    int tx = tid & 15, ty = tid >> 4;

    load_tile_T(proj, projT, 1.0f);
    load_tile_T(qs + ((long)b * Q + q0) * 128, XT, NORMALIZER);
    if (tid < 128) ksum_s[tid] = g_ksum[b * 128 + tid];
    __syncthreads();

    if (tid < 128) {
        float h = 0.0f;
#pragma unroll 8
        for (int d = 0; d < 128; d++) {
            float x = XT[d * LD + tid];
            h += x * x;
        }
        hbuf[tid] = 0.5f * h;
    }
    __syncthreads();

    // P^T[m][q] = sum_d projT[d][m] * XT[d][q]
    float p[8][8];
#pragma unroll
    for (int r = 0; r < 8; r++)
#pragma unroll
        for (int c = 0; c < 8; c++) p[r][c] = 0.0f;
    gemm128(projT, XT, p, ty * 8, tx * 8);

    // ST[m][q] = exp(P^T - h[q]) * rsqrt(m)
#pragma unroll
    for (int r = 0; r < 8; r++) {
        int mrow = ty * 8 + r;
        float4 o0, o1;
        o0.x = __expf(p[r][0] - hbuf[tx * 8 + 0]) * RSQRT_M;
        o0.y = __expf(p[r][1] - hbuf[tx * 8 + 1]) * RSQRT_M;
        o0.z = __expf(p[r][2] - hbuf[tx * 8 + 2]) * RSQRT_M;
        o0.w = __expf(p[r][3] - hbuf[tx * 8 + 3]) * RSQRT_M;
        o1.x = __expf(p[r][4] - hbuf[tx * 8 + 4]) * RSQRT_M;
        o1.y = __expf(p[r][5] - hbuf[tx * 8 + 5]) * RSQRT_M;
        o1.z = __expf(p[r][6] - hbuf[tx * 8 + 6]) * RSQRT_M;
        o1.w = __expf(p[r][7] - hbuf[tx * 8 + 7]) * RSQRT_M;
        *(float4*)(ST + mrow * LD + tx * 8)     = o0;
        *(float4*)(ST + mrow * LD + tx * 8 + 4) = o1;
    }
    __syncthreads();   // ST ready; projT reads complete

    // KV tile into projT buffer; den[q] = sum_m ST[m][q]*ksum[m] in parallel.
    load_tile_RM(g_kv + b * 128 * 128, projT);
    if (tid < 128) {
        float dn = 0.0f;
#pragma unroll 8
        for (int m = 0; m < 128; m++) dn += ST[m * LD + tid] * ksum_s[m];
        denb[tid] = (dn < EPS_DEN) ? EPS_DEN : dn;
    }
    __syncthreads();

    // out[q][v] = sum_m ST[m][q] * KV[m][v] / den[q]
    float acc[8][8];
#pragma unroll
    for (int r = 0; r < 8; r++)
#pragma unroll
        for (int c = 0; c < 8; c++) acc[r][c] = 0.0f;
    gemm128(ST, projT, acc, ty * 8, tx * 8);

#pragma unroll
    for (int r = 0; r < 8; r++) {
        int q = q0 + ty * 8 + r;
        float inv = 1.0f / denb[ty * 8 + r];
        float4 o0, o1;
        o0.x = acc[r][0] * inv; o0.y = acc[r][1] * inv;
        o0.z = acc[r][2] * inv; o0.w = acc[r][3] * inv;
        o1.x = acc[r][4] * inv; o1.y = acc[r][5] * inv;
        o1.z = acc[r][6] * inv; o1.w = acc[r][7] * inv;
        float* orow = out + ((long)b * Q + q) * 128 + tx * 8;
        *(float4*)(orow)     = o0;
        *(float4*)(orow + 4) = o1;
    }
}

// ---------------------------------------------------------------------------
extern "C" void kernel_launch(void* const* d_in, const int* in_sizes, int n_in,
                              void* d_out, int out_size) {
    const float* qs   = (const float*)d_in[0];
    const float* ks   = (const float*)d_in[1];
    const float* vs   = (const float*)d_in[2];
    const float* proj = (const float*)d_in[3];
    const void*  vl   = d_in[4];

    int B = in_sizes[4];
    if (B > MAX_B) B = MAX_B;
    int Q = in_sizes[0] / (B * 128);
    int K = in_sizes[1] / (B * 128);

    const int smem_bytes = (3 * ROWF + 512) * (int)sizeof(float);  // 204800 B
    cudaFuncSetAttribute(kv_kernel,  cudaFuncAttributeMaxDynamicSharedMemorySize, smem_bytes);
    cudaFuncSetAttribute(out_kernel, cudaFuncAttributeMaxDynamicSharedMemorySize, smem_bytes);

    int n_init = B * 128 * 128;
    init_kernel<<<(n_init + 255) / 256, 256>>>(B);

    dim3 grid_kv(K / TILE, B);
    kv_kernel<<<grid_kv, 256, smem_bytes>>>(ks, vs, proj, vl, K);

    dim3 grid_out(Q / TILE, B);
    out_kernel<<<grid_out, 256, smem_bytes>>>(qs, proj, (float*)d_out, Q);
}

// round 6
// speedup vs baseline: 2.0121x; 2.0121x over previous
#include <cuda_runtime.h>
#include <cuda_bf16.h>
#include <cstdint>

// FAVOR+ linear attention via mma.sync.m16n8k16 bf16 3-pass split (sm_100
// baseline PTX -- tcgen05 is rejected by this harness's compile target).
//   init_kernel : zero g_kv / g_ksum
//   kv_kernel   : P^T[m][k] = proj@Ks^T ; S^T = exp(P^T - h[k])*mask*rsqrt(m)
//                 kv[m][v] += S^T @ V   (register-accumulated over 4 k-tiles)
//   out_kernel  : P[q][m] = Xq@proj^T ; Q' = exp(P - h[q])*rsqrt(m)
//                 out = (Q' @ kv) / max(Q'.ksum, EPS)

#define MAX_B 8
__device__ float g_kv[MAX_B * 128 * 128];   // [b][m][v]
__device__ float g_ksum[MAX_B * 128];

static constexpr float NORM = 0.29730177875068026f;  // 128^-0.25
static constexpr float RSQ  = 0.08838834764831845f;  // 1/sqrt(128)
static constexpr float EPSD = 1e-6f;

#define ROWB 272                     // 136 bf16 per smem row: 17*16B, 4-bank skew
#define TILE_BYTES (128 * ROWB)      // 34816
#define SMEM_DYN (2048 + 6 * TILE_BYTES)

// ---------------------------------------------------------------------------
__device__ __forceinline__ uint32_t smem_u32(const void* p) {
    return (uint32_t)__cvta_generic_to_shared(p);
}

__device__ __forceinline__ void ldsm4(uint32_t addr, uint32_t* r) {
    asm volatile("ldmatrix.sync.aligned.m8n8.x4.shared.b16 {%0,%1,%2,%3}, [%4];"
                 : "=r"(r[0]), "=r"(r[1]), "=r"(r[2]), "=r"(r[3]) : "r"(addr) : "memory");
}
__device__ __forceinline__ void ldsm4t(uint32_t addr, uint32_t* r) {
    asm volatile("ldmatrix.sync.aligned.m8n8.x4.trans.shared.b16 {%0,%1,%2,%3}, [%4];"
                 : "=r"(r[0]), "=r"(r[1]), "=r"(r[2]), "=r"(r[3]) : "r"(addr) : "memory");
}
__device__ __forceinline__ void mma16816(float* c, const uint32_t* a,
                                         uint32_t b0, uint32_t b1) {
    asm volatile(
        "mma.sync.aligned.m16n8k16.row.col.f32.bf16.bf16.f32 "
        "{%0,%1,%2,%3}, {%4,%5,%6,%7}, {%8,%9}, {%0,%1,%2,%3};"
        : "+f"(c[0]), "+f"(c[1]), "+f"(c[2]), "+f"(c[3])
        : "r"(a[0]), "r"(a[1]), "r"(a[2]), "r"(a[3]), "r"(b0), "r"(b1));
}

// fp32 pair -> packed bf16x2 hi and lo (residual) words; a = even element.
__device__ __forceinline__ void cvt_split2(float a, float b, uint32_t& hi, uint32_t& lo) {
    __nv_bfloat16 ha = __float2bfloat16_rn(a), hb = __float2bfloat16_rn(b);
    __nv_bfloat16 la = __float2bfloat16_rn(a - __bfloat162float(ha));
    __nv_bfloat16 lb = __float2bfloat16_rn(b - __bfloat162float(hb));
    hi = ((uint32_t)__bfloat16_as_ushort(hb) << 16) | __bfloat16_as_ushort(ha);
    lo = ((uint32_t)__bfloat16_as_ushort(lb) << 16) | __bfloat16_as_ushort(la);
}

// Load 128x128 fp32 gmem tile (row stride 128) -> row-major split bf16 tiles
// [row][col], 136-elem stride. Optionally computes hb[r]=0.5*||scale*row||^2.
__device__ __forceinline__ void load_cvt_rm(const float* __restrict__ g,
                                            char* hi_t, char* lo_t,
                                            float scale, float* hb) {
    int w = threadIdx.x >> 5, l = threadIdx.x & 31;
#pragma unroll 4
    for (int i = 0; i < 16; i++) {
        int r = w * 16 + i;
        float4 v = *(const float4*)(g + r * 128 + l * 4);
        v.x *= scale; v.y *= scale; v.z *= scale; v.w *= scale;
        if (hb) {
            float hp = v.x * v.x + v.y * v.y + v.z * v.z + v.w * v.w;
#pragma unroll
            for (int s = 16; s; s >>= 1) hp += __shfl_xor_sync(0xFFFFFFFFu, hp, s);
            if (l == 0) hb[r] = 0.5f * hp;
        }
        uint32_t h0, l0, h1, l1;
        cvt_split2(v.x, v.y, h0, l0);
        cvt_split2(v.z, v.w, h1, l1);
        uint32_t off = (uint32_t)(r * ROWB + l * 8);
        *(uint2*)(hi_t + off) = make_uint2(h0, h1);
        *(uint2*)(lo_t + off) = make_uint2(l0, l1);
    }
}

// 3-pass split GEMM: C[16 tiles][4] += A(128x128) @ B^T, A=[m][k] row-major,
// B=[n][k] row-major (transb=false) or B=[k][n] row-major (transb=true).
__device__ __forceinline__ void gemm3p(float C[16][4],
                                       uint32_t Ah, uint32_t Al,
                                       uint32_t Bh, uint32_t Bl,
                                       bool transb, int w, int lane) {
    uint32_t a_off = (uint32_t)((16 * w + (lane & 15)) * ROWB + ((lane >> 4) & 1) * 16);
    uint32_t b_off = transb
        ? (uint32_t)(((lane & 7) + (((lane >> 3) & 1) << 3)) * ROWB + ((lane >> 4) & 1) * 16)
        : (uint32_t)(((lane & 7) + (((lane >> 4) & 1) << 3)) * ROWB + ((lane >> 3) & 1) * 16);
#pragma unroll 1
    for (int ks = 0; ks < 8; ks++) {
        uint32_t ah[4], al[4];
        ldsm4(Ah + a_off + ks * 32, ah);
        ldsm4(Al + a_off + ks * 32, al);
#pragma unroll
        for (int nt2 = 0; nt2 < 8; nt2++) {
            uint32_t bo = transb ? (b_off + nt2 * 32 + ks * 16 * ROWB)
                                 : (b_off + nt2 * 16 * ROWB + ks * 32);
            uint32_t bh[4], bl[4];
            if (transb) { ldsm4t(Bh + bo, bh); ldsm4t(Bl + bo, bl); }
            else        { ldsm4 (Bh + bo, bh); ldsm4 (Bl + bo, bl); }
            mma16816(C[2 * nt2],     ah, bh[0], bh[1]);
            mma16816(C[2 * nt2],     ah, bl[0], bl[1]);
            mma16816(C[2 * nt2],     al, bh[0], bh[1]);
            mma16816(C[2 * nt2 + 1], ah, bh[2], bh[3]);
            mma16816(C[2 * nt2 + 1], ah, bl[2], bl[3]);
            mma16816(C[2 * nt2 + 1], al, bh[2], bh[3]);
        }
    }
}

__device__ __forceinline__ int get_vl(const void* p, int b, int K) {
    const int* pi = (const int*)p;
    bool is64 = (pi[1] == 0) && (pi[3] == 0) && (pi[5] == 0) && (pi[7] == 0) &&
                (pi[0] >= 0 && pi[0] <= K) && (pi[2] >= 0 && pi[2] <= K) &&
                (pi[4] >= 0 && pi[4] <= K) && (pi[6] >= 0 && pi[6] <= K);
    return is64 ? pi[2 * b] : pi[b];
}

__device__ __forceinline__ float expc(float e) { return __expf(fminf(e, 80.0f)); }

// ---------------------------------------------------------------------------
__global__ void init_kernel(int b_count) {
    int i = blockIdx.x * blockDim.x + threadIdx.x;
    if (i < b_count * 128 * 128) g_kv[i] = 0.0f;
    if (i < b_count * 128) g_ksum[i] = 0.0f;
}

// ---------------------------------------------------------------------------
// kv_kernel: grid (K/512, B), 256 threads, 4 k-tiles per CTA.
// ---------------------------------------------------------------------------
__global__ void __launch_bounds__(256)
kv_kernel(const float* __restrict__ ks, const float* __restrict__ vs,
          const float* __restrict__ proj, const void* __restrict__ vl, int K) {
    extern __shared__ char smr[];
    float* hbuf = (float*)smr;                    // [128]
    char* tiles = smr + 2048;
    char *T0 = tiles,                *T1 = tiles + TILE_BYTES,
         *T2 = tiles + 2*TILE_BYTES, *T3 = tiles + 3*TILE_BYTES,
         *T4 = tiles + 4*TILE_BYTES, *T5 = tiles + 5*TILE_BYTES;
    uint32_t u0 = smem_u32(T0), u1 = smem_u32(T1), u2 = smem_u32(T2),
             u3 = smem_u32(T3), u4 = smem_u32(T4), u5 = smem_u32(T5);

    int tid = threadIdx.x, w = tid >> 5, lane = tid & 31;
    int b = blockIdx.y;
    int vlb = get_vl(vl, b, K);

    load_cvt_rm(proj, T0, T1, 1.0f, nullptr);     // proj persists

    float C2[16][4];
#pragma unroll
    for (int t = 0; t < 16; t++)
#pragma unroll
        for (int e = 0; e < 4; e++) C2[t][e] = 0.0f;
    float ksp0 = 0.0f, ksp1 = 0.0f;

    int r0 = 16 * w + (lane >> 2);                // fragment row (m)

    for (int it = 0; it < 4; it++) {
        int kt0 = (blockIdx.x * 4 + it) * 128;
        load_cvt_rm(ks + ((long)b * K + kt0) * 128, T2, T3, NORM, hbuf);
        load_cvt_rm(vs + ((long)b * K + kt0) * 128, T4, T5, 1.0f, nullptr);
        __syncthreads();

        float C1[16][4];
#pragma unroll
        for (int t = 0; t < 16; t++)
#pragma unroll
            for (int e = 0; e < 4; e++) C1[t][e] = 0.0f;
        gemm3p(C1, u0, u1, u2, u3, false, w, lane);   // P^T[m][k]
        __syncthreads();                               // GEMM1 reads of X done

        // S^T[m][k] = exp(P^T - h[k]) * mask * rsqrt(m), stored over X tiles.
#pragma unroll
        for (int t = 0; t < 16; t++) {
            int c0 = t * 8 + (lane & 3) * 2;
            float m0 = ((kt0 + c0)     < vlb) ? RSQ : 0.0f;
            float m1 = ((kt0 + c0 + 1) < vlb) ? RSQ : 0.0f;
            float h0 = hbuf[c0], h1 = hbuf[c0 + 1];
            float s00 = expc(C1[t][0] - h0) * m0;
            float s01 = expc(C1[t][1] - h1) * m1;
            float s10 = expc(C1[t][2] - h0) * m0;
            float s11 = expc(C1[t][3] - h1) * m1;
            ksp0 += s00 + s01;
            ksp1 += s10 + s11;
            uint32_t H0, L0, H1, L1;
            cvt_split2(s00, s01, H0, L0);
            cvt_split2(s10, s11, H1, L1);
            uint32_t off0 = (uint32_t)(r0 * ROWB + c0 * 2);
            uint32_t off1 = off0 + 8 * ROWB;
            *(uint32_t*)(T2 + off0) = H0;  *(uint32_t*)(T3 + off0) = L0;
            *(uint32_t*)(T2 + off1) = H1;  *(uint32_t*)(T3 + off1) = L1;
        }
        __syncthreads();

        gemm3p(C2, u2, u3, u4, u5, true, w, lane);    // kv[m][v] += S^T @ V
        __syncthreads();                               // tiles reused next iter
    }

    // Flush kv fragments (rows m, cols v) to g_kv[b][m][v].
    float* kvb = g_kv + b * 128 * 128;
#pragma unroll
    for (int t = 0; t < 16; t++) {
        int v0 = t * 8 + (lane & 3) * 2;
        atomicAdd(kvb + r0 * 128 + v0,           C2[t][0]);
        atomicAdd(kvb + r0 * 128 + v0 + 1,       C2[t][1]);
        atomicAdd(kvb + (r0 + 8) * 128 + v0,     C2[t][2]);
        atomicAdd(kvb + (r0 + 8) * 128 + v0 + 1, C2[t][3]);
    }
    ksp0 += __shfl_xor_sync(0xFFFFFFFFu, ksp0, 1);
    ksp0 += __shfl_xor_sync(0xFFFFFFFFu, ksp0, 2);
    ksp1 += __shfl_xor_sync(0xFFFFFFFFu, ksp1, 1);
    ksp1 += __shfl_xor_sync(0xFFFFFFFFu, ksp1, 2);
    if ((lane & 3) == 0) {
        atomicAdd(&g_ksum[b * 128 + r0], ksp0);
        atomicAdd(&g_ksum[b * 128 + r0 + 8], ksp1);
    }
}

// ---------------------------------------------------------------------------
// out_kernel: grid (Q/512, B), 256 threads, 4 q-tiles per CTA.
// ---------------------------------------------------------------------------
__global__ void __launch_bounds__(256)
out_kernel(const float* __restrict__ qs, const float* __restrict__ proj,
           float* __restrict__ out, int Q) {
    extern __shared__ char smr[];
    float* hbuf   = (float*)smr;                  // [128]
    float* ksum_s = (float*)(smr + 512);          // [128]
    float* denb   = (float*)(smr + 1024);         // [128]
    char* tiles = smr + 2048;
    char *T0 = tiles,                *T1 = tiles + TILE_BYTES,
         *T2 = tiles + 2*TILE_BYTES, *T3 = tiles + 3*TILE_BYTES,
         *T4 = tiles + 4*TILE_BYTES, *T5 = tiles + 5*TILE_BYTES;
    uint32_t u0 = smem_u32(T0), u1 = smem_u32(T1), u2 = smem_u32(T2),
             u3 = smem_u32(T3), u4 = smem_u32(T4), u5 = smem_u32(T5);

    int tid = threadIdx.x, w = tid >> 5, lane = tid & 31;
    int b = blockIdx.y;

    load_cvt_rm(proj, T0, T1, 1.0f, nullptr);
    load_cvt_rm(g_kv + b * 128 * 128, T4, T5, 1.0f, nullptr);   // kv [m][v]
    if (tid < 128) ksum_s[tid] = g_ksum[b * 128 + tid];

    int r0 = 16 * w + (lane >> 2);                // fragment row (q)

    for (int it = 0; it < 4; it++) {
        int q0 = (blockIdx.x * 4 + it) * 128;
        load_cvt_rm(qs + ((long)b * Q + q0) * 128, T2, T3, NORM, hbuf);
        __syncthreads();

        float C1[16][4];
#pragma unroll
        for (int t = 0; t < 16; t++)
#pragma unroll
            for (int e = 0; e < 4; e++) C1[t][e] = 0.0f;
        gemm3p(C1, u2, u3, u0, u1, false, w, lane);   // P[q][m]
        __syncthreads();

        // Q'[q][m] = exp(P - h[q]) * rsqrt(m); den[q] = sum_m Q' * ksum[m].
        float hq0 = hbuf[r0], hq1 = hbuf[r0 + 8];
        float d0 = 0.0f, d1 = 0.0f;
#pragma unroll
        for (int t = 0; t < 16; t++) {
            int c0 = t * 8 + (lane & 3) * 2;
            float k0 = ksum_s[c0], k1 = ksum_s[c0 + 1];
            float s00 = expc(C1[t][0] - hq0) * RSQ;
            float s01 = expc(C1[t][1] - hq0) * RSQ;
            float s10 = expc(C1[t][2] - hq1) * RSQ;
            float s11 = expc(C1[t][3] - hq1) * RSQ;
            d0 += s00 * k0 + s01 * k1;
            d1 += s10 * k0 + s11 * k1;
            uint32_t H0, L0, H1, L1;
            cvt_split2(s00, s01, H0, L0);
            cvt_split2(s10, s11, H1, L1);
            uint32_t off0 = (uint32_t)(r0 * ROWB + c0 * 2);
            uint32_t off1 = off0 + 8 * ROWB;
            *(uint32_t*)(T2 + off0) = H0;  *(uint32_t*)(T3 + off0) = L0;
            *(uint32_t*)(T2 + off1) = H1;  *(uint32_t*)(T3 + off1) = L1;
        }
        d0 += __shfl_xor_sync(0xFFFFFFFFu, d0, 1);
        d0 += __shfl_xor_sync(0xFFFFFFFFu, d0, 2);
        d1 += __shfl_xor_sync(0xFFFFFFFFu, d1, 1);
        d1 += __shfl_xor_sync(0xFFFFFFFFu, d1, 2);
        if ((lane & 3) == 0) {
            denb[r0]     = (d0 < EPSD) ? EPSD : d0;
            denb[r0 + 8] = (d1 < EPSD) ? EPSD : d1;
        }
        __syncthreads();

        float C2[16][4];
#pragma unroll
        for (int t = 0; t < 16; t++)
#pragma unroll
            for (int e = 0; e < 4; e++) C2[t][e] = 0.0f;
        gemm3p(C2, u2, u3, u4, u5, true, w, lane);    // out[q][v]

        float inv0 = 1.0f / denb[r0], inv1 = 1.0f / denb[r0 + 8];
        float* orow0 = out + ((long)b * Q + q0 + r0) * 128;
        float* orow1 = orow0 + 8 * 128;
#pragma unroll
        for (int t = 0; t < 16; t++) {
            int v0 = t * 8 + (lane & 3) * 2;
            float2 o0 = make_float2(C2[t][0] * inv0, C2[t][1] * inv0);
            float2 o1 = make_float2(C2[t][2] * inv1, C2[t][3] * inv1);
            *(float2*)(orow0 + v0) = o0;
            *(float2*)(orow1 + v0) = o1;
        }
        __syncthreads();                               // before next-iter load
    }
}

// ---------------------------------------------------------------------------
extern "C" void kernel_launch(void* const* d_in, const int* in_sizes, int n_in,
                              void* d_out, int out_size) {
    const float* qs   = (const float*)d_in[0];
    const float* ks   = (const float*)d_in[1];
    const float* vs   = (const float*)d_in[2];
    const float* proj = (const float*)d_in[3];
    const void*  vl   = d_in[4];

    int B = in_sizes[4];
    if (B > MAX_B) B = MAX_B;
    int Q = in_sizes[0] / (B * 128);
    int K = in_sizes[1] / (B * 128);

    cudaFuncSetAttribute(kv_kernel,  cudaFuncAttributeMaxDynamicSharedMemorySize, SMEM_DYN);
    cudaFuncSetAttribute(out_kernel, cudaFuncAttributeMaxDynamicSharedMemorySize, SMEM_DYN);

    int n_init = B * 128 * 128;
    init_kernel<<<(n_init + 255) / 256, 256>>>(B);

    dim3 gkv(K / 512, B);
    kv_kernel<<<gkv, 256, SMEM_DYN>>>(ks, vs, proj, vl, K);

    dim3 gout(Q / 512, B);
    out_kernel<<<gout, 256, SMEM_DYN>>>(qs, proj, (float*)d_out, Q);
}

// round 7
// speedup vs baseline: 2.4270x; 1.2062x over previous
#include <cuda_runtime.h>
#include <cuda_bf16.h>
#include <cuda_fp16.h>
#include <cstdint>

// FAVOR+ linear attention via mma.sync.m16n8k16 (sm_100 baseline PTX).
// GEMM1 (feature map): 3-pass bf16 split (exp amplifies absolute error).
// GEMM2 (S@V / Q'@kv): 2-pass fp16 (A plain fp16, B fp16 hi+lo split).
// Global loads software-pipelined under the MMA phases.

#define MAX_B 8
__device__ float g_kv[MAX_B * 128 * 128];   // [b][m][v]
__device__ float g_ksum[MAX_B * 128];

static constexpr float NORM = 0.29730177875068026f;  // 128^-0.25
static constexpr float RSQ  = 0.08838834764831845f;  // 1/sqrt(128)
static constexpr float EPSD = 1e-6f;

#define ROWB 272                     // 136 elems/row (b16): 17*16B, 4-bank skew
#define TILE_BYTES (128 * ROWB)      // 34816
#define SMEM_DYN (2048 + 6 * TILE_BYTES)

// ---------------------------------------------------------------------------
__device__ __forceinline__ uint32_t smem_u32(const void* p) {
    return (uint32_t)__cvta_generic_to_shared(p);
}
__device__ __forceinline__ void ldsm4(uint32_t addr, uint32_t* r) {
    asm volatile("ldmatrix.sync.aligned.m8n8.x4.shared.b16 {%0,%1,%2,%3}, [%4];"
                 : "=r"(r[0]), "=r"(r[1]), "=r"(r[2]), "=r"(r[3]) : "r"(addr) : "memory");
}
__device__ __forceinline__ void ldsm4t(uint32_t addr, uint32_t* r) {
    asm volatile("ldmatrix.sync.aligned.m8n8.x4.trans.shared.b16 {%0,%1,%2,%3}, [%4];"
                 : "=r"(r[0]), "=r"(r[1]), "=r"(r[2]), "=r"(r[3]) : "r"(addr) : "memory");
}
__device__ __forceinline__ void mma_bf(float* c, const uint32_t* a,
                                       uint32_t b0, uint32_t b1) {
    asm volatile(
        "mma.sync.aligned.m16n8k16.row.col.f32.bf16.bf16.f32 "
        "{%0,%1,%2,%3}, {%4,%5,%6,%7}, {%8,%9}, {%0,%1,%2,%3};"
        : "+f"(c[0]), "+f"(c[1]), "+f"(c[2]), "+f"(c[3])
        : "r"(a[0]), "r"(a[1]), "r"(a[2]), "r"(a[3]), "r"(b0), "r"(b1));
}
__device__ __forceinline__ void mma_fp(float* c, const uint32_t* a,
                                       uint32_t b0, uint32_t b1) {
    asm volatile(
        "mma.sync.aligned.m16n8k16.row.col.f32.f16.f16.f32 "
        "{%0,%1,%2,%3}, {%4,%5,%6,%7}, {%8,%9}, {%0,%1,%2,%3};"
        : "+f"(c[0]), "+f"(c[1]), "+f"(c[2]), "+f"(c[3])
        : "r"(a[0]), "r"(a[1]), "r"(a[2]), "r"(a[3]), "r"(b0), "r"(b1));
}

// bf16 hi/lo split of an fp32 pair (a = even element).
__device__ __forceinline__ void cvt_split2(float a, float b, uint32_t& hi, uint32_t& lo) {
    __nv_bfloat16 ha = __float2bfloat16_rn(a), hb = __float2bfloat16_rn(b);
    __nv_bfloat16 la = __float2bfloat16_rn(a - __bfloat162float(ha));
    __nv_bfloat16 lb = __float2bfloat16_rn(b - __bfloat162float(hb));
    hi = ((uint32_t)__bfloat16_as_ushort(hb) << 16) | __bfloat16_as_ushort(ha);
    lo = ((uint32_t)__bfloat16_as_ushort(lb) << 16) | __bfloat16_as_ushort(la);
}
__device__ __forceinline__ uint32_t f16x2(float a, float b) {
    __half2 h = __floats2half2_rn(a, b);
    return *reinterpret_cast<uint32_t*>(&h);
}
// fp16 hi/lo split of an fp32 pair.
__device__ __forceinline__ void cvt_split2h(float a, float b, uint32_t& hi, uint32_t& lo) {
    __half ha = __float2half_rn(a), hb = __float2half_rn(b);
    hi = ((uint32_t)__half_as_ushort(hb) << 16) | __half_as_ushort(ha);
    lo = f16x2(a - __half2float(ha), b - __half2float(hb));
}

// 16 x float4 per thread covers one 128x128 fp32 tile (row stride 128).
__device__ __forceinline__ void ldg_tile(const float* __restrict__ g, float4* vr) {
    int w = threadIdx.x >> 5, l = threadIdx.x & 31;
#pragma unroll
    for (int i = 0; i < 16; i++)
        vr[i] = *(const float4*)(g + (w * 16 + i) * 128 + l * 4);
}
// Convert regs -> row-major bf16 split tiles; optional hb[r]=0.5*||scale*row||^2.
__device__ __forceinline__ void st_tile_bf16(const float4* vr, char* hi_t, char* lo_t,
                                             float scale, float* hb) {
    int w = threadIdx.x >> 5, l = threadIdx.x & 31;
#pragma unroll
    for (int i = 0; i < 16; i++) {
        int r = w * 16 + i;
        float4 v = vr[i];
        v.x *= scale; v.y *= scale; v.z *= scale; v.w *= scale;
        if (hb) {
            float hp = v.x * v.x + v.y * v.y + v.z * v.z + v.w * v.w;
#pragma unroll
            for (int s = 16; s; s >>= 1) hp += __shfl_xor_sync(0xFFFFFFFFu, hp, s);
            if (l == 0) hb[r] = 0.5f * hp;
        }
        uint32_t h0, l0, h1, l1;
        cvt_split2(v.x, v.y, h0, l0);
        cvt_split2(v.z, v.w, h1, l1);
        uint32_t off = (uint32_t)(r * ROWB + l * 8);
        *(uint2*)(hi_t + off) = make_uint2(h0, h1);
        *(uint2*)(lo_t + off) = make_uint2(l0, l1);
    }
}
// Convert regs -> row-major fp16 split tiles (scale 1).
__device__ __forceinline__ void st_tile_f16s(const float4* vr, char* hi_t, char* lo_t) {
    int w = threadIdx.x >> 5, l = threadIdx.x & 31;
#pragma unroll
    for (int i = 0; i < 16; i++) {
        int r = w * 16 + i;
        float4 v = vr[i];
        uint32_t h0, l0, h1, l1;
        cvt_split2h(v.x, v.y, h0, l0);
        cvt_split2h(v.z, v.w, h1, l1);
        uint32_t off = (uint32_t)(r * ROWB + l * 8);
        *(uint2*)(hi_t + off) = make_uint2(h0, h1);
        *(uint2*)(lo_t + off) = make_uint2(l0, l1);
    }
}

// 3-pass bf16 split GEMM (non-trans B): C += A @ B^T, A=[m][k], B=[n][k].
__device__ __forceinline__ void gemm3p(float C[16][4],
                                       uint32_t Ah, uint32_t Al,
                                       uint32_t Bh, uint32_t Bl, int w, int lane) {
    uint32_t a_off = (uint32_t)((16 * w + (lane & 15)) * ROWB + ((lane >> 4) & 1) * 16);
    uint32_t b_off = (uint32_t)(((lane & 7) + (((lane >> 4) & 1) << 3)) * ROWB +
                                ((lane >> 3) & 1) * 16);
#pragma unroll 1
    for (int ks = 0; ks < 8; ks++) {
        uint32_t ah[4], al[4];
        ldsm4(Ah + a_off + ks * 32, ah);
        ldsm4(Al + a_off + ks * 32, al);
#pragma unroll
        for (int nt2 = 0; nt2 < 8; nt2++) {
            uint32_t bo = b_off + nt2 * 16 * ROWB + ks * 32;
            uint32_t bh[4], bl[4];
            ldsm4(Bh + bo, bh);
            ldsm4(Bl + bo, bl);
            mma_bf(C[2 * nt2],     ah, bh[0], bh[1]);
            mma_bf(C[2 * nt2],     ah, bl[0], bl[1]);
            mma_bf(C[2 * nt2],     al, bh[0], bh[1]);
            mma_bf(C[2 * nt2 + 1], ah, bh[2], bh[3]);
            mma_bf(C[2 * nt2 + 1], ah, bl[2], bl[3]);
            mma_bf(C[2 * nt2 + 1], al, bh[2], bh[3]);
        }
    }
}
// 2-pass fp16 GEMM (trans B): C += A @ B, A=[m][k] plain fp16, B=[k][n] split.
__device__ __forceinline__ void gemm2p(float C[16][4], uint32_t Au,
                                       uint32_t Bh, uint32_t Bl, int w, int lane) {
    uint32_t a_off = (uint32_t)((16 * w + (lane & 15)) * ROWB + ((lane >> 4) & 1) * 16);
    uint32_t b_off = (uint32_t)(((lane & 7) + (((lane >> 3) & 1) << 3)) * ROWB +
                                ((lane >> 4) & 1) * 16);
#pragma unroll 1
    for (int ks = 0; ks < 8; ks++) {
        uint32_t a[4];
        ldsm4(Au + a_off + ks * 32, a);
#pragma unroll
        for (int nt2 = 0; nt2 < 8; nt2++) {
            uint32_t bo = b_off + nt2 * 32 + ks * 16 * ROWB;
            uint32_t bh[4], bl[4];
            ldsm4t(Bh + bo, bh);
            ldsm4t(Bl + bo, bl);
            mma_fp(C[2 * nt2],     a, bh[0], bh[1]);
            mma_fp(C[2 * nt2],     a, bl[0], bl[1]);
            mma_fp(C[2 * nt2 + 1], a, bh[2], bh[3]);
            mma_fp(C[2 * nt2 + 1], a, bl[2], bl[3]);
        }
    }
}

__device__ __forceinline__ int get_vl(const void* p, int b, int K) {
    const int* pi = (const int*)p;
    bool is64 = (pi[1] == 0) && (pi[3] == 0) && (pi[5] == 0) && (pi[7] == 0) &&
                (pi[0] >= 0 && pi[0] <= K) && (pi[2] >= 0 && pi[2] <= K) &&
                (pi[4] >= 0 && pi[4] <= K) && (pi[6] >= 0 && pi[6] <= K);
    return is64 ? pi[2 * b] : pi[b];
}
__device__ __forceinline__ float expc(float e) { return __expf(fminf(e, 80.0f)); }

// ---------------------------------------------------------------------------
__global__ void init_kernel(int b_count) {
    int i = blockIdx.x * blockDim.x + threadIdx.x;
    int nkv4 = b_count * 128 * 32;
    if (i < nkv4) ((float4*)g_kv)[i] = make_float4(0.f, 0.f, 0.f, 0.f);
    if (i < b_count * 32) ((float4*)g_ksum)[i] = make_float4(0.f, 0.f, 0.f, 0.f);
}

// ---------------------------------------------------------------------------
// kv_kernel: grid (K/512, B), 256 threads, 4 k-tiles per CTA.
// ---------------------------------------------------------------------------
__global__ void __launch_bounds__(256)
kv_kernel(const float* __restrict__ ks, const float* __restrict__ vs,
          const float* __restrict__ proj, const void* __restrict__ vl, int K) {
    extern __shared__ char smr[];
    float* hbuf = (float*)smr;                    // [128]
    char* tiles = smr + 2048;
    char *T0 = tiles,                *T1 = tiles + TILE_BYTES,
         *T2 = tiles + 2*TILE_BYTES, *T3 = tiles + 3*TILE_BYTES,
         *T4 = tiles + 4*TILE_BYTES, *T5 = tiles + 5*TILE_BYTES;
    uint32_t u0 = smem_u32(T0), u1 = smem_u32(T1), u2 = smem_u32(T2),
             u3 = smem_u32(T3), u4 = smem_u32(T4), u5 = smem_u32(T5);

    int tid = threadIdx.x, w = tid >> 5, lane = tid & 31;
    int b = blockIdx.y;
    int vlb = get_vl(vl, b, K);
    int r0 = 16 * w + (lane >> 2);                // fragment row (m)

    {   // proj (persists) + first ks tile
        float4 pr[16];
        ldg_tile(proj, pr);
        st_tile_bf16(pr, T0, T1, 1.0f, nullptr);
        float4 kr[16];
        ldg_tile(ks + ((long)b * K + blockIdx.x * 512) * 128, kr);
        st_tile_bf16(kr, T2, T3, NORM, hbuf);
    }
    __syncthreads();

    float C2[16][4];
#pragma unroll
    for (int t = 0; t < 16; t++)
#pragma unroll
        for (int e = 0; e < 4; e++) C2[t][e] = 0.0f;
    float ksp0 = 0.0f, ksp1 = 0.0f;

    for (int it = 0; it < 4; it++) {
        int kt0 = (blockIdx.x * 4 + it) * 128;

        // Prefetch V under GEMM1.
        float4 vr[16];
        ldg_tile(vs + ((long)b * K + kt0) * 128, vr);

        float C1[16][4];
#pragma unroll
        for (int t = 0; t < 16; t++)
#pragma unroll
            for (int e = 0; e < 4; e++) C1[t][e] = 0.0f;
        gemm3p(C1, u0, u1, u2, u3, w, lane);      // P^T[m][k] = proj . X^T

        st_tile_f16s(vr, T4, T5);                 // V -> fp16 split (T4/T5 free)
        __syncthreads();                          // GEMM1 reads done; V ready

        // Epilogue: S^T[m][k] = exp(P^T - h[k]) * mask * rsqrt(m) -> T2 (fp16).
#pragma unroll
        for (int t = 0; t < 16; t++) {
            int c0 = t * 8 + (lane & 3) * 2;
            float m0 = ((kt0 + c0)     < vlb) ? RSQ : 0.0f;
            float m1 = ((kt0 + c0 + 1) < vlb) ? RSQ : 0.0f;
            float h0 = hbuf[c0], h1 = hbuf[c0 + 1];
            float s00 = expc(C1[t][0] - h0) * m0;
            float s01 = expc(C1[t][1] - h1) * m1;
            float s10 = expc(C1[t][2] - h0) * m0;
            float s11 = expc(C1[t][3] - h1) * m1;
            ksp0 += s00 + s01;
            ksp1 += s10 + s11;
            uint32_t off0 = (uint32_t)(r0 * ROWB + c0 * 2);
            *(uint32_t*)(T2 + off0)            = f16x2(s00, s01);
            *(uint32_t*)(T2 + off0 + 8 * ROWB) = f16x2(s10, s11);
        }

        // Prefetch next ks tile under GEMM2.
        float4 kr[16];
        bool pf = (it < 3);
        if (pf) ldg_tile(ks + ((long)b * K + kt0 + 128) * 128, kr);
        __syncthreads();                          // S complete

        gemm2p(C2, u2, u4, u5, w, lane);          // kv[m][v] += S^T @ V
        __syncthreads();                          // all GEMM2 reads done

        if (pf) st_tile_bf16(kr, T2, T3, NORM, hbuf);
    }

    float* kvb = g_kv + b * 128 * 128;
#pragma unroll
    for (int t = 0; t < 16; t++) {
        int v0 = t * 8 + (lane & 3) * 2;
        atomicAdd(kvb + r0 * 128 + v0,           C2[t][0]);
        atomicAdd(kvb + r0 * 128 + v0 + 1,       C2[t][1]);
        atomicAdd(kvb + (r0 + 8) * 128 + v0,     C2[t][2]);
        atomicAdd(kvb + (r0 + 8) * 128 + v0 + 1, C2[t][3]);
    }
    ksp0 += __shfl_xor_sync(0xFFFFFFFFu, ksp0, 1);
    ksp0 += __shfl_xor_sync(0xFFFFFFFFu, ksp0, 2);
    ksp1 += __shfl_xor_sync(0xFFFFFFFFu, ksp1, 1);
    ksp1 += __shfl_xor_sync(0xFFFFFFFFu, ksp1, 2);
    if ((lane & 3) == 0) {
        atomicAdd(&g_ksum[b * 128 + r0], ksp0);
        atomicAdd(&g_ksum[b * 128 + r0 + 8], ksp1);
    }
}

// ---------------------------------------------------------------------------
// out_kernel: grid (Q/512, B), 256 threads, 4 q-tiles per CTA.
// ---------------------------------------------------------------------------
__global__ void __launch_bounds__(256)
out_kernel(const float* __restrict__ qs, const float* __restrict__ proj,
           float* __restrict__ out, int Q) {
    extern __shared__ char smr[];
    float* hbuf   = (float*)smr;                  // [128]
    float* ksum_s = (float*)(smr + 512);          // [128]
    float* denb   = (float*)(smr + 1024);         // [128]
    char* tiles = smr + 2048;
    char *T0 = tiles,                *T1 = tiles + TILE_BYTES,
         *T2 = tiles + 2*TILE_BYTES, *T3 = tiles + 3*TILE_BYTES,
         *T4 = tiles + 4*TILE_BYTES, *T5 = tiles + 5*TILE_BYTES;
    uint32_t u0 = smem_u32(T0), u1 = smem_u32(T1), u2 = smem_u32(T2),
             u3 = smem_u32(T3), u4 = smem_u32(T4), u5 = smem_u32(T5);

    int tid = threadIdx.x, w = tid >> 5, lane = tid & 31;
    int b = blockIdx.y;
    int r0 = 16 * w + (lane >> 2);                // fragment row (q)

    {   // proj (bf16 split), kv (fp16 split), ksum, first qs tile
        float4 pr[16];
        ldg_tile(proj, pr);
        st_tile_bf16(pr, T0, T1, 1.0f, nullptr);
        float4 kvr[16];
        ldg_tile(g_kv + b * 128 * 128, kvr);
        st_tile_f16s(kvr, T4, T5);
        float4 qr[16];
        ldg_tile(qs + ((long)b * Q + blockIdx.x * 512) * 128, qr);
        st_tile_bf16(qr, T2, T3, NORM, hbuf);
        if (tid < 128) ksum_s[tid] = g_ksum[b * 128 + tid];
    }
    __syncthreads();

    for (int it = 0; it < 4; it++) {
        int q0 = (blockIdx.x * 4 + it) * 128;

        float C1[16][4];
#pragma unroll
        for (int t = 0; t < 16; t++)
#pragma unroll
            for (int e = 0; e < 4; e++) C1[t][e] = 0.0f;
        gemm3p(C1, u2, u3, u0, u1, w, lane);      // P[q][m] = X . proj^T
        __syncthreads();                          // T2 writable

        // Q'[q][m] (fp16) -> T2 ; den[q] = sum_m Q' * ksum[m].
        float hq0 = hbuf[r0], hq1 = hbuf[r0 + 8];
        float d0 = 0.0f, d1 = 0.0f;
#pragma unroll
        for (int t = 0; t < 16; t++) {
            int c0 = t * 8 + (lane & 3) * 2;
            float k0 = ksum_s[c0], k1 = ksum_s[c0 + 1];
            float s00 = expc(C1[t][0] - hq0) * RSQ;
            float s01 = expc(C1[t][1] - hq0) * RSQ;
            float s10 = expc(C1[t][2] - hq1) * RSQ;
            float s11 = expc(C1[t][3] - hq1) * RSQ;
            d0 += s00 * k0 + s01 * k1;
            d1 += s10 * k0 + s11 * k1;
            uint32_t off0 = (uint32_t)(r0 * ROWB + c0 * 2);
            *(uint32_t*)(T2 + off0)            = f16x2(s00, s01);
            *(uint32_t*)(T2 + off0 + 8 * ROWB) = f16x2(s10, s11);
        }
        d0 += __shfl_xor_sync(0xFFFFFFFFu, d0, 1);
        d0 += __shfl_xor_sync(0xFFFFFFFFu, d0, 2);
        d1 += __shfl_xor_sync(0xFFFFFFFFu, d1, 1);
        d1 += __shfl_xor_sync(0xFFFFFFFFu, d1, 2);
        if ((lane & 3) == 0) {
            denb[r0]     = (d0 < EPSD) ? EPSD : d0;
            denb[r0 + 8] = (d1 < EPSD) ? EPSD : d1;
        }

        // Prefetch next qs tile under GEMM2.
        float4 qr[16];
        bool pf = (it < 3);
        if (pf) ldg_tile(qs + ((long)b * Q + q0 + 128) * 128, qr);
        __syncthreads();                          // Q' + denb ready

        float C2[16][4];
#pragma unroll
        for (int t = 0; t < 16; t++)
#pragma unroll
            for (int e = 0; e < 4; e++) C2[t][e] = 0.0f;
        gemm2p(C2, u2, u4, u5, w, lane);          // out[q][v] = Q' @ kv

        float inv0 = 1.0f / denb[r0], inv1 = 1.0f / denb[r0 + 8];
        float* orow0 = out + ((long)b * Q + q0 + r0) * 128;
        float* orow1 = orow0 + 8 * 128;
#pragma unroll
        for (int t = 0; t < 16; t++) {
            int v0 = t * 8 + (lane & 3) * 2;
            *(float2*)(orow0 + v0) = make_float2(C2[t][0] * inv0, C2[t][1] * inv0);
            *(float2*)(orow1 + v0) = make_float2(C2[t][2] * inv1, C2[t][3] * inv1);
        }
        __syncthreads();                          // GEMM2 reads done

        if (pf) st_tile_bf16(qr, T2, T3, NORM, hbuf);
    }
}

// ---------------------------------------------------------------------------
extern "C" void kernel_launch(void* const* d_in, const int* in_sizes, int n_in,
                              void* d_out, int out_size) {
    const float* qs   = (const float*)d_in[0];
    const float* ks   = (const float*)d_in[1];
    const float* vs   = (const float*)d_in[2];
    const float* proj = (const float*)d_in[3];
    const void*  vl   = d_in[4];

    int B = in_sizes[4];
    if (B > MAX_B) B = MAX_B;
    int Q = in_sizes[0] / (B * 128);
    int K = in_sizes[1] / (B * 128);

    cudaFuncSetAttribute(kv_kernel,  cudaFuncAttributeMaxDynamicSharedMemorySize, SMEM_DYN);
    cudaFuncSetAttribute(out_kernel, cudaFuncAttributeMaxDynamicSharedMemorySize, SMEM_DYN);

    int n4 = B * 128 * 32;
    init_kernel<<<(n4 + 255) / 256, 256>>>(B);

    dim3 gkv(K / 512, B);
    kv_kernel<<<gkv, 256, SMEM_DYN>>>(ks, vs, proj, vl, K);

    dim3 gout(Q / 512, B);
    out_kernel<<<gout, 256, SMEM_DYN>>>(qs, proj, (float*)d_out, Q);
}

// round 8
// speedup vs baseline: 2.7317x; 1.1255x over previous
#include <cuda_runtime.h>
#include <cuda_bf16.h>
#include <cuda_fp16.h>
#include <cstdint>

// FAVOR+ linear attention via mma.sync.m16n8k16 (sm_100 baseline PTX).
// GEMM1 (feature map): 3-pass bf16 split (exp amplifies absolute P error;
//   2-pass leaves ~9.4e-4 -> must stay 3-pass).
// GEMM2 (S@V / Q'@kv): 1-pass fp16 (A=S/Q' plain, B=V/kv plain; kv scaled
//   1/16 for fp16 range, unscaled in the final divide).
// S/Q' live in their own tile (T5) -> only 2 syncs per iteration.

#define MAX_B 8
__device__ float g_kv[MAX_B * 128 * 128];   // [b][m][v]
__device__ float g_ksum[MAX_B * 128];

static constexpr float NORM = 0.29730177875068026f;  // 128^-0.25
static constexpr float RSQ  = 0.08838834764831845f;  // 1/sqrt(128)
static constexpr float EPSD = 1e-6f;
static constexpr float KV_SCALE   = 0.0625f;         // 1/16
static constexpr float KV_UNSCALE = 16.0f;

#define ROWB 272                     // 136 elems/row (b16): 17*16B, 4-bank skew
#define TILE_BYTES (128 * ROWB)      // 34816
#define SMEM_DYN (2048 + 6 * TILE_BYTES)

// ---------------------------------------------------------------------------
__device__ __forceinline__ uint32_t smem_u32(const void* p) {
    return (uint32_t)__cvta_generic_to_shared(p);
}
__device__ __forceinline__ void ldsm4(uint32_t addr, uint32_t* r) {
    asm volatile("ldmatrix.sync.aligned.m8n8.x4.shared.b16 {%0,%1,%2,%3}, [%4];"
                 : "=r"(r[0]), "=r"(r[1]), "=r"(r[2]), "=r"(r[3]) : "r"(addr) : "memory");
}
__device__ __forceinline__ void ldsm4t(uint32_t addr, uint32_t* r) {
    asm volatile("ldmatrix.sync.aligned.m8n8.x4.trans.shared.b16 {%0,%1,%2,%3}, [%4];"
                 : "=r"(r[0]), "=r"(r[1]), "=r"(r[2]), "=r"(r[3]) : "r"(addr) : "memory");
}
__device__ __forceinline__ void mma_bf(float* c, const uint32_t* a,
                                       uint32_t b0, uint32_t b1) {
    asm volatile(
        "mma.sync.aligned.m16n8k16.row.col.f32.bf16.bf16.f32 "
        "{%0,%1,%2,%3}, {%4,%5,%6,%7}, {%8,%9}, {%0,%1,%2,%3};"
        : "+f"(c[0]), "+f"(c[1]), "+f"(c[2]), "+f"(c[3])
        : "r"(a[0]), "r"(a[1]), "r"(a[2]), "r"(a[3]), "r"(b0), "r"(b1));
}
__device__ __forceinline__ void mma_fp(float* c, const uint32_t* a,
                                       uint32_t b0, uint32_t b1) {
    asm volatile(
        "mma.sync.aligned.m16n8k16.row.col.f32.f16.f16.f32 "
        "{%0,%1,%2,%3}, {%4,%5,%6,%7}, {%8,%9}, {%0,%1,%2,%3};"
        : "+f"(c[0]), "+f"(c[1]), "+f"(c[2]), "+f"(c[3])
        : "r"(a[0]), "r"(a[1]), "r"(a[2]), "r"(a[3]), "r"(b0), "r"(b1));
}

// bf16 hi/lo split of an fp32 pair (a = even element).
__device__ __forceinline__ void cvt_split2(float a, float b, uint32_t& hi, uint32_t& lo) {
    __nv_bfloat16 ha = __float2bfloat16_rn(a), hb = __float2bfloat16_rn(b);
    __nv_bfloat16 la = __float2bfloat16_rn(a - __bfloat162float(ha));
    __nv_bfloat16 lb = __float2bfloat16_rn(b - __bfloat162float(hb));
    hi = ((uint32_t)__bfloat16_as_ushort(hb) << 16) | __bfloat16_as_ushort(ha);
    lo = ((uint32_t)__bfloat16_as_ushort(lb) << 16) | __bfloat16_as_ushort(la);
}
__device__ __forceinline__ uint32_t f16x2(float a, float b) {
    __half2 h = __floats2half2_rn(a, b);
    return *reinterpret_cast<uint32_t*>(&h);
}

// 16 x float4 per thread covers one 128x128 fp32 tile (row stride 128).
__device__ __forceinline__ void ldg_tile(const float* __restrict__ g, float4* vr) {
    int w = threadIdx.x >> 5, l = threadIdx.x & 31;
#pragma unroll
    for (int i = 0; i < 16; i++)
        vr[i] = *(const float4*)(g + (w * 16 + i) * 128 + l * 4);
}
// Regs -> row-major bf16 split tiles; optional hb[r]=0.5*||scale*row||^2.
__device__ __forceinline__ void st_tile_bf16(const float4* vr, char* hi_t, char* lo_t,
                                             float scale, float* hb) {
    int w = threadIdx.x >> 5, l = threadIdx.x & 31;
#pragma unroll
    for (int i = 0; i < 16; i++) {
        int r = w * 16 + i;
        float4 v = vr[i];
        v.x *= scale; v.y *= scale; v.z *= scale; v.w *= scale;
        if (hb) {
            float hp = v.x * v.x + v.y * v.y + v.z * v.z + v.w * v.w;
#pragma unroll
            for (int s = 16; s; s >>= 1) hp += __shfl_xor_sync(0xFFFFFFFFu, hp, s);
            if (l == 0) hb[r] = 0.5f * hp;
        }
        uint32_t h0, l0, h1, l1;
        cvt_split2(v.x, v.y, h0, l0);
        cvt_split2(v.z, v.w, h1, l1);
        uint32_t off = (uint32_t)(r * ROWB + l * 8);
        *(uint2*)(hi_t + off) = make_uint2(h0, h1);
        *(uint2*)(lo_t + off) = make_uint2(l0, l1);
    }
}
// Regs -> row-major plain fp16 tile (scaled).
__device__ __forceinline__ void st_tile_f16(const float4* vr, char* t, float scale) {
    int w = threadIdx.x >> 5, l = threadIdx.x & 31;
#pragma unroll
    for (int i = 0; i < 16; i++) {
        int r = w * 16 + i;
        float4 v = vr[i];
        uint32_t off = (uint32_t)(r * ROWB + l * 8);
        *(uint2*)(t + off) = make_uint2(f16x2(v.x * scale, v.y * scale),
                                        f16x2(v.z * scale, v.w * scale));
    }
}

// 3-pass bf16 split GEMM (non-trans B): C += A @ B^T, A=[m][k], B=[n][k].
__device__ __forceinline__ void gemm3p(float C[16][4],
                                       uint32_t Ah, uint32_t Al,
                                       uint32_t Bh, uint32_t Bl, int w, int lane) {
    uint32_t a_off = (uint32_t)((16 * w + (lane & 15)) * ROWB + ((lane >> 4) & 1) * 16);
    uint32_t b_off = (uint32_t)(((lane & 7) + (((lane >> 4) & 1) << 3)) * ROWB +
                                ((lane >> 3) & 1) * 16);
#pragma unroll 1
    for (int ks = 0; ks < 8; ks++) {
        uint32_t ah[4], al[4];
        ldsm4(Ah + a_off + ks * 32, ah);
        ldsm4(Al + a_off + ks * 32, al);
#pragma unroll
        for (int nt2 = 0; nt2 < 8; nt2++) {
            uint32_t bo = b_off + nt2 * 16 * ROWB + ks * 32;
            uint32_t bh[4], bl[4];
            ldsm4(Bh + bo, bh);
            ldsm4(Bl + bo, bl);
            mma_bf(C[2 * nt2],     ah, bh[0], bh[1]);
            mma_bf(C[2 * nt2],     ah, bl[0], bl[1]);
            mma_bf(C[2 * nt2],     al, bh[0], bh[1]);
            mma_bf(C[2 * nt2 + 1], ah, bh[2], bh[3]);
            mma_bf(C[2 * nt2 + 1], ah, bl[2], bl[3]);
            mma_bf(C[2 * nt2 + 1], al, bh[2], bh[3]);
        }
    }
}
// 1-pass fp16 GEMM (trans B): C += A @ B, A=[m][k] plain, B=[k][n] plain.
__device__ __forceinline__ void gemm1p(float C[16][4], uint32_t Au, uint32_t Bu,
                                       int w, int lane) {
    uint32_t a_off = (uint32_t)((16 * w + (lane & 15)) * ROWB + ((lane >> 4) & 1) * 16);
    uint32_t b_off = (uint32_t)(((lane & 7) + (((lane >> 3) & 1) << 3)) * ROWB +
                                ((lane >> 4) & 1) * 16);
#pragma unroll 1
    for (int ks = 0; ks < 8; ks++) {
        uint32_t a[4];
        ldsm4(Au + a_off + ks * 32, a);
#pragma unroll
        for (int nt2 = 0; nt2 < 8; nt2++) {
            uint32_t bo = b_off + nt2 * 32 + ks * 16 * ROWB;
            uint32_t bb[4];
            ldsm4t(Bu + bo, bb);
            mma_fp(C[2 * nt2],     a, bb[0], bb[1]);
            mma_fp(C[2 * nt2 + 1], a, bb[2], bb[3]);
        }
    }
}

__device__ __forceinline__ int get_vl(const void* p, int b, int K) {
    const int* pi = (const int*)p;
    bool is64 = (pi[1] == 0) && (pi[3] == 0) && (pi[5] == 0) && (pi[7] == 0) &&
                (pi[0] >= 0 && pi[0] <= K) && (pi[2] >= 0 && pi[2] <= K) &&
                (pi[4] >= 0 && pi[4] <= K) && (pi[6] >= 0 && pi[6] <= K);
    return is64 ? pi[2 * b] : pi[b];
}
__device__ __forceinline__ float expc(float e) { return __expf(fminf(e, 80.0f)); }

// ---------------------------------------------------------------------------
__global__ void init_kernel(int b_count) {
    int i = blockIdx.x * blockDim.x + threadIdx.x;
    int nkv4 = b_count * 128 * 32;
    if (i < nkv4) ((float4*)g_kv)[i] = make_float4(0.f, 0.f, 0.f, 0.f);
    if (i < b_count * 32) ((float4*)g_ksum)[i] = make_float4(0.f, 0.f, 0.f, 0.f);
}

// ---------------------------------------------------------------------------
// kv_kernel: grid (K/512, B), 256 threads, 4 k-tiles per CTA.
// Tiles: T0/T1 proj bf16 hi/lo, T2/T3 X bf16 hi/lo, T4 V fp16, T5 S fp16.
// ---------------------------------------------------------------------------
__global__ void __launch_bounds__(256)
kv_kernel(const float* __restrict__ ks, const float* __restrict__ vs,
          const float* __restrict__ proj, const void* __restrict__ vl, int K) {
    extern __shared__ char smr[];
    float* hbuf = (float*)smr;                    // [128]
    char* tiles = smr + 2048;
    char *T0 = tiles,                *T1 = tiles + TILE_BYTES,
         *T2 = tiles + 2*TILE_BYTES, *T3 = tiles + 3*TILE_BYTES,
         *T4 = tiles + 4*TILE_BYTES, *T5 = tiles + 5*TILE_BYTES;
    uint32_t u0 = smem_u32(T0), u1 = smem_u32(T1), u2 = smem_u32(T2),
             u3 = smem_u32(T3), u4 = smem_u32(T4), u5 = smem_u32(T5);

    int tid = threadIdx.x, w = tid >> 5, lane = tid & 31;
    int b = blockIdx.y;
    int vlb = get_vl(vl, b, K);
    int r0 = 16 * w + (lane >> 2);                // fragment row (m)

    {   // proj (persists) + first ks tile
        float4 pr[16];
        ldg_tile(proj, pr);
        st_tile_bf16(pr, T0, T1, 1.0f, nullptr);
        float4 kr[16];
        ldg_tile(ks + ((long)b * K + blockIdx.x * 512) * 128, kr);
        st_tile_bf16(kr, T2, T3, NORM, hbuf);
    }
    __syncthreads();

    float C2[16][4];
#pragma unroll
    for (int t = 0; t < 16; t++)
#pragma unroll
        for (int e = 0; e < 4; e++) C2[t][e] = 0.0f;
    float ksp0 = 0.0f, ksp1 = 0.0f;

    for (int it = 0; it < 4; it++) {
        int kt0 = (blockIdx.x * 4 + it) * 128;

        // Prefetch V under GEMM1.
        float4 vr[16];
        ldg_tile(vs + ((long)b * K + kt0) * 128, vr);

        float C1[16][4];
#pragma unroll
        for (int t = 0; t < 16; t++)
#pragma unroll
            for (int e = 0; e < 4; e++) C1[t][e] = 0.0f;
        gemm3p(C1, u0, u1, u2, u3, w, lane);      // P^T[m][k] = proj . X^T

        st_tile_f16(vr, T4, 1.0f);                // V fp16 (T4 free since prev sync)

        // Epilogue: S^T[m][k] -> T5 (fp16), ksum accum.
#pragma unroll
        for (int t = 0; t < 16; t++) {
            int c0 = t * 8 + (lane & 3) * 2;
            float m0 = ((kt0 + c0)     < vlb) ? RSQ : 0.0f;
            float m1 = ((kt0 + c0 + 1) < vlb) ? RSQ : 0.0f;
            float h0 = hbuf[c0], h1 = hbuf[c0 + 1];
            float s00 = expc(C1[t][0] - h0) * m0;
            float s01 = expc(C1[t][1] - h1) * m1;
            float s10 = expc(C1[t][2] - h0) * m0;
            float s11 = expc(C1[t][3] - h1) * m1;
            ksp0 += s00 + s01;
            ksp1 += s10 + s11;
            uint32_t off0 = (uint32_t)(r0 * ROWB + c0 * 2);
            *(uint32_t*)(T5 + off0)            = f16x2(s00, s01);
            *(uint32_t*)(T5 + off0 + 8 * ROWB) = f16x2(s10, s11);
        }
        __syncthreads();                          // #1: S+V visible; X reads done

        // Prefetch next ks tile under GEMM2.
        float4 kr[16];
        bool pf = (it < 3);
        if (pf) ldg_tile(ks + ((long)b * K + kt0 + 128) * 128, kr);

        gemm1p(C2, u5, u4, w, lane);              // kv[m][v] += S^T @ V

        if (pf) st_tile_bf16(kr, T2, T3, NORM, hbuf);  // X(it+1); GEMM1 readers done
        __syncthreads();                          // #2: GEMM2 + X(it+1) complete
    }

    float* kvb = g_kv + b * 128 * 128;
#pragma unroll
    for (int t = 0; t < 16; t++) {
        int v0 = t * 8 + (lane & 3) * 2;
        atomicAdd(kvb + r0 * 128 + v0,           C2[t][0]);
        atomicAdd(kvb + r0 * 128 + v0 + 1,       C2[t][1]);
        atomicAdd(kvb + (r0 + 8) * 128 + v0,     C2[t][2]);
        atomicAdd(kvb + (r0 + 8) * 128 + v0 + 1, C2[t][3]);
    }
    ksp0 += __shfl_xor_sync(0xFFFFFFFFu, ksp0, 1);
    ksp0 += __shfl_xor_sync(0xFFFFFFFFu, ksp0, 2);
    ksp1 += __shfl_xor_sync(0xFFFFFFFFu, ksp1, 1);
    ksp1 += __shfl_xor_sync(0xFFFFFFFFu, ksp1, 2);
    if ((lane & 3) == 0) {
        atomicAdd(&g_ksum[b * 128 + r0], ksp0);
        atomicAdd(&g_ksum[b * 128 + r0 + 8], ksp1);
    }
}

// ---------------------------------------------------------------------------
// out_kernel: grid (Q/512, B), 256 threads, 4 q-tiles per CTA.
// Tiles: T0/T1 proj bf16 hi/lo, T2/T3 Q bf16 hi/lo, T4 kv fp16 (x1/16), T5 Q' fp16.
// ---------------------------------------------------------------------------
__global__ void __launch_bounds__(256)
out_kernel(const float* __restrict__ qs, const float* __restrict__ proj,
           float* __restrict__ out, int Q) {
    extern __shared__ char smr[];
    float* hbuf   = (float*)smr;                  // [128]
    float* ksum_s = (float*)(smr + 512);          // [128]
    float* denb   = (float*)(smr + 1024);         // [128]
    char* tiles = smr + 2048;
    char *T0 = tiles,                *T1 = tiles + TILE_BYTES,
         *T2 = tiles + 2*TILE_BYTES, *T3 = tiles + 3*TILE_BYTES,
         *T4 = tiles + 4*TILE_BYTES, *T5 = tiles + 5*TILE_BYTES;
    uint32_t u0 = smem_u32(T0), u1 = smem_u32(T1), u2 = smem_u32(T2),
             u3 = smem_u32(T3), u4 = smem_u32(T4), u5 = smem_u32(T5);

    int tid = threadIdx.x, w = tid >> 5, lane = tid & 31;
    int b = blockIdx.y;
    int r0 = 16 * w + (lane >> 2);                // fragment row (q)

    {   // proj bf16 split, kv fp16 (scaled), ksum, first qs tile
        float4 pr[16];
        ldg_tile(proj, pr);
        st_tile_bf16(pr, T0, T1, 1.0f, nullptr);
        float4 kvr[16];
        ldg_tile(g_kv + b * 128 * 128, kvr);
        st_tile_f16(kvr, T4, KV_SCALE);
        float4 qr[16];
        ldg_tile(qs + ((long)b * Q + blockIdx.x * 512) * 128, qr);
        st_tile_bf16(qr, T2, T3, NORM, hbuf);
        if (tid < 128) ksum_s[tid] = g_ksum[b * 128 + tid];
    }
    __syncthreads();

    for (int it = 0; it < 4; it++) {
        int q0 = (blockIdx.x * 4 + it) * 128;

        float C1[16][4];
#pragma unroll
        for (int t = 0; t < 16; t++)
#pragma unroll
            for (int e = 0; e < 4; e++) C1[t][e] = 0.0f;
        gemm3p(C1, u2, u3, u0, u1, w, lane);      // P[q][m] = X . proj^T

        // Q'[q][m] (fp16) -> T5 ; den[q] = sum_m Q' * ksum[m].
        float hq0 = hbuf[r0], hq1 = hbuf[r0 + 8];
        float d0 = 0.0f, d1 = 0.0f;
#pragma unroll
        for (int t = 0; t < 16; t++) {
            int c0 = t * 8 + (lane & 3) * 2;
            float k0 = ksum_s[c0], k1 = ksum_s[c0 + 1];
            float s00 = expc(C1[t][0] - hq0) * RSQ;
            float s01 = expc(C1[t][1] - hq0) * RSQ;
            float s10 = expc(C1[t][2] - hq1) * RSQ;
            float s11 = expc(C1[t][3] - hq1) * RSQ;
            d0 += s00 * k0 + s01 * k1;
            d1 += s10 * k0 + s11 * k1;
            uint32_t off0 = (uint32_t)(r0 * ROWB + c0 * 2);
            *(uint32_t*)(T5 + off0)            = f16x2(s00, s01);
            *(uint32_t*)(T5 + off0 + 8 * ROWB) = f16x2(s10, s11);
        }
        d0 += __shfl_xor_sync(0xFFFFFFFFu, d0, 1);
        d0 += __shfl_xor_sync(0xFFFFFFFFu, d0, 2);
        d1 += __shfl_xor_sync(0xFFFFFFFFu, d1, 1);
        d1 += __shfl_xor_sync(0xFFFFFFFFu, d1, 2);
        if ((lane & 3) == 0) {
            denb[r0]     = (d0 < EPSD) ? EPSD : d0;
            denb[r0 + 8] = (d1 < EPSD) ? EPSD : d1;
        }
        __syncthreads();                          // #1: Q' + denb visible

        // Prefetch next qs tile under GEMM2.
        float4 qr[16];
        bool pf = (it < 3);
        if (pf) ldg_tile(qs + ((long)b * Q + q0 + 128) * 128, qr);

        float C2[16][4];
#pragma unroll
        for (int t = 0; t < 16; t++)
#pragma unroll
            for (int e = 0; e < 4; e++) C2[t][e] = 0.0f;
        gemm1p(C2, u5, u4, w, lane);              // out[q][v] = Q' @ kv_scaled

        float inv0 = KV_UNSCALE / denb[r0], inv1 = KV_UNSCALE / denb[r0 + 8];
        float* orow0 = out + ((long)b * Q + q0 + r0) * 128;
        float* orow1 = orow0 + 8 * 128;
#pragma unroll
        for (int t = 0; t < 16; t++) {
            int v0 = t * 8 + (lane & 3) * 2;
            *(float2*)(orow0 + v0) = make_float2(C2[t][0] * inv0, C2[t][1] * inv0);
            *(float2*)(orow1 + v0) = make_float2(C2[t][2] * inv1, C2[t][3] * inv1);
        }

        if (pf) st_tile_bf16(qr, T2, T3, NORM, hbuf);  // Q(it+1); GEMM1 readers done
        __syncthreads();                          // #2: GEMM2 + Q(it+1) complete
    }
}

// ---------------------------------------------------------------------------
extern "C" void kernel_launch(void* const* d_in, const int* in_sizes, int n_in,
                              void* d_out, int out_size) {
    const float* qs   = (const float*)d_in[0];
    const float* ks   = (const float*)d_in[1];
    const float* vs   = (const float*)d_in[2];
    const float* proj = (const float*)d_in[3];
    const void*  vl   = d_in[4];

    int B = in_sizes[4];
    if (B > MAX_B) B = MAX_B;
    int Q = in_sizes[0] / (B * 128);
    int K = in_sizes[1] / (B * 128);

    cudaFuncSetAttribute(kv_kernel,  cudaFuncAttributeMaxDynamicSharedMemorySize, SMEM_DYN);
    cudaFuncSetAttribute(out_kernel, cudaFuncAttributeMaxDynamicSharedMemorySize, SMEM_DYN);

    int n4 = B * 128 * 32;
    init_kernel<<<(n4 + 255) / 256, 256>>>(B);

    dim3 gkv(K / 512, B);
    kv_kernel<<<gkv, 256, SMEM_DYN>>>(ks, vs, proj, vl, K);

    dim3 gout(Q / 512, B);
    out_kernel<<<gout, 256, SMEM_DYN>>>(qs, proj, (float*)d_out, Q);
}

// round 9
// speedup vs baseline: 3.0594x; 1.1200x over previous
#include <cuda_runtime.h>
#include <cuda_bf16.h>
#include <cuda_fp16.h>
#include <cstdint>

// FAVOR+ linear attention via mma.sync.m16n8k16 (sm_100 baseline PTX).
// GEMM1: 3-pass bf16 split (must stay 3-pass: 2-pass adds ~8e-4 -> bust).
// GEMM2: 1-pass fp16 (kv scaled 1/16 for range, unscaled in final divide).
// Prefetches split into half-tiles interleaved with ranged GEMM halves to
// cap register pressure (full-tile prefetch held 64 regs across GEMM1).

#define MAX_B 8
__device__ float g_kv[MAX_B * 128 * 128];   // [b][m][v]
__device__ float g_ksum[MAX_B * 128];

static constexpr float NORM = 0.29730177875068026f;  // 128^-0.25
static constexpr float RSQ  = 0.08838834764831845f;  // 1/sqrt(128)
static constexpr float EPSD = 1e-6f;
static constexpr float KV_SCALE   = 0.0625f;
static constexpr float KV_UNSCALE = 16.0f;

#define ROWB 272                     // 136 elems/row (b16): 17*16B, 4-bank skew
#define TILE_BYTES (128 * ROWB)      // 34816
#define SMEM_DYN (2048 + 6 * TILE_BYTES)

// ---------------------------------------------------------------------------
__device__ __forceinline__ uint32_t smem_u32(const void* p) {
    return (uint32_t)__cvta_generic_to_shared(p);
}
__device__ __forceinline__ void ldsm4(uint32_t addr, uint32_t* r) {
    asm volatile("ldmatrix.sync.aligned.m8n8.x4.shared.b16 {%0,%1,%2,%3}, [%4];"
                 : "=r"(r[0]), "=r"(r[1]), "=r"(r[2]), "=r"(r[3]) : "r"(addr) : "memory");
}
__device__ __forceinline__ void ldsm4t(uint32_t addr, uint32_t* r) {
    asm volatile("ldmatrix.sync.aligned.m8n8.x4.trans.shared.b16 {%0,%1,%2,%3}, [%4];"
                 : "=r"(r[0]), "=r"(r[1]), "=r"(r[2]), "=r"(r[3]) : "r"(addr) : "memory");
}
__device__ __forceinline__ void mma_bf(float* c, const uint32_t* a,
                                       uint32_t b0, uint32_t b1) {
    asm volatile(
        "mma.sync.aligned.m16n8k16.row.col.f32.bf16.bf16.f32 "
        "{%0,%1,%2,%3}, {%4,%5,%6,%7}, {%8,%9}, {%0,%1,%2,%3};"
        : "+f"(c[0]), "+f"(c[1]), "+f"(c[2]), "+f"(c[3])
        : "r"(a[0]), "r"(a[1]), "r"(a[2]), "r"(a[3]), "r"(b0), "r"(b1));
}
__device__ __forceinline__ void mma_fp(float* c, const uint32_t* a,
                                       uint32_t b0, uint32_t b1) {
    asm volatile(
        "mma.sync.aligned.m16n8k16.row.col.f32.f16.f16.f32 "
        "{%0,%1,%2,%3}, {%4,%5,%6,%7}, {%8,%9}, {%0,%1,%2,%3};"
        : "+f"(c[0]), "+f"(c[1]), "+f"(c[2]), "+f"(c[3])
        : "r"(a[0]), "r"(a[1]), "r"(a[2]), "r"(a[3]), "r"(b0), "r"(b1));
}

// bf16 hi/lo split of an fp32 pair (a = even element): packed cvt + shift
// reconstruction (hi bf16 -> f32 is just <<16), residual packed cvt.
__device__ __forceinline__ void cvt_split2(float a, float b, uint32_t& hi, uint32_t& lo) {
    uint32_t h2;
    asm("cvt.rn.bf16x2.f32 %0, %1, %2;" : "=r"(h2) : "f"(b), "f"(a));
    float ha = __uint_as_float(h2 << 16);
    float hb = __uint_as_float(h2 & 0xFFFF0000u);
    uint32_t l2;
    asm("cvt.rn.bf16x2.f32 %0, %1, %2;" : "=r"(l2) : "f"(b - hb), "f"(a - ha));
    hi = h2; lo = l2;
}
__device__ __forceinline__ uint32_t f16x2(float a, float b) {
    __half2 h = __floats2half2_rn(a, b);
    return *reinterpret_cast<uint32_t*>(&h);
}

// Half-tile (8 rows/thread-group) global load: 32 regs instead of 64.
__device__ __forceinline__ void ldg_half(const float* __restrict__ g, float4* vr, int hf) {
    int w = threadIdx.x >> 5, l = threadIdx.x & 31;
#pragma unroll
    for (int i = 0; i < 8; i++)
        vr[i] = *(const float4*)(g + (w * 16 + hf * 8 + i) * 128 + l * 4);
}
// Half-tile -> bf16 split tiles; optional hb[r] = 0.5*||scale*row||^2.
__device__ __forceinline__ void st_half_bf16(const float4* vr, char* hi_t, char* lo_t,
                                             float scale, float* hb, int hf) {
    int w = threadIdx.x >> 5, l = threadIdx.x & 31;
#pragma unroll
    for (int i = 0; i < 8; i++) {
        int r = w * 16 + hf * 8 + i;
        float4 v = vr[i];
        v.x *= scale; v.y *= scale; v.z *= scale; v.w *= scale;
        if (hb) {
            float hp = v.x * v.x + v.y * v.y + v.z * v.z + v.w * v.w;
#pragma unroll
            for (int s = 16; s; s >>= 1) hp += __shfl_xor_sync(0xFFFFFFFFu, hp, s);
            if (l == 0) hb[r] = 0.5f * hp;
        }
        uint32_t h0, l0, h1, l1;
        cvt_split2(v.x, v.y, h0, l0);
        cvt_split2(v.z, v.w, h1, l1);
        uint32_t off = (uint32_t)(r * ROWB + l * 8);
        *(uint2*)(hi_t + off) = make_uint2(h0, h1);
        *(uint2*)(lo_t + off) = make_uint2(l0, l1);
    }
}
// Half-tile -> plain fp16 tile (scaled).
__device__ __forceinline__ void st_half_f16(const float4* vr, char* t, float scale, int hf) {
    int w = threadIdx.x >> 5, l = threadIdx.x & 31;
#pragma unroll
    for (int i = 0; i < 8; i++) {
        int r = w * 16 + hf * 8 + i;
        float4 v = vr[i];
        uint32_t off = (uint32_t)(r * ROWB + l * 8);
        *(uint2*)(t + off) = make_uint2(f16x2(v.x * scale, v.y * scale),
                                        f16x2(v.z * scale, v.w * scale));
    }
}

// 3-pass bf16 split GEMM over ks range: C += A @ B^T, A=[m][k], B=[n][k].
// Same-accumulator MMAs interleaved across the C-tile pair (distance 2).
__device__ __forceinline__ void gemm3p(float C[16][4],
                                       uint32_t Ah, uint32_t Al,
                                       uint32_t Bh, uint32_t Bl,
                                       int w, int lane, int ks0, int ks1) {
    uint32_t a_off = (uint32_t)((16 * w + (lane & 15)) * ROWB + ((lane >> 4) & 1) * 16);
    uint32_t b_off = (uint32_t)(((lane & 7) + (((lane >> 4) & 1) << 3)) * ROWB +
                                ((lane >> 3) & 1) * 16);
#pragma unroll 1
    for (int ks = ks0; ks < ks1; ks++) {
        uint32_t ah[4], al[4];
        ldsm4(Ah + a_off + ks * 32, ah);
        ldsm4(Al + a_off + ks * 32, al);
#pragma unroll
        for (int nt2 = 0; nt2 < 8; nt2++) {
            uint32_t bo = b_off + nt2 * 16 * ROWB + ks * 32;
            uint32_t bh[4], bl[4];
            ldsm4(Bh + bo, bh);
            ldsm4(Bl + bo, bl);
            mma_bf(C[2 * nt2],     ah, bh[0], bh[1]);
            mma_bf(C[2 * nt2 + 1], ah, bh[2], bh[3]);
            mma_bf(C[2 * nt2],     ah, bl[0], bl[1]);
            mma_bf(C[2 * nt2 + 1], ah, bl[2], bl[3]);
            mma_bf(C[2 * nt2],     al, bh[0], bh[1]);
            mma_bf(C[2 * nt2 + 1], al, bh[2], bh[3]);
        }
    }
}
// 1-pass fp16 GEMM over ks range (trans B): C += A @ B.
__device__ __forceinline__ void gemm1p(float C[16][4], uint32_t Au, uint32_t Bu,
                                       int w, int lane, int ks0, int ks1) {
    uint32_t a_off = (uint32_t)((16 * w + (lane & 15)) * ROWB + ((lane >> 4) & 1) * 16);
    uint32_t b_off = (uint32_t)(((lane & 7) + (((lane >> 3) & 1) << 3)) * ROWB +
                                ((lane >> 4) & 1) * 16);
#pragma unroll 1
    for (int ks = ks0; ks < ks1; ks++) {
        uint32_t a[4];
        ldsm4(Au + a_off + ks * 32, a);
#pragma unroll
        for (int nt2 = 0; nt2 < 8; nt2++) {
            uint32_t bo = b_off + nt2 * 32 + ks * 16 * ROWB;
            uint32_t bb[4];
            ldsm4t(Bu + bo, bb);
            mma_fp(C[2 * nt2],     a, bb[0], bb[1]);
            mma_fp(C[2 * nt2 + 1], a, bb[2], bb[3]);
        }
    }
}

__device__ __forceinline__ int get_vl(const void* p, int b, int K) {
    const int* pi = (const int*)p;
    bool is64 = (pi[1] == 0) && (pi[3] == 0) && (pi[5] == 0) && (pi[7] == 0) &&
                (pi[0] >= 0 && pi[0] <= K) && (pi[2] >= 0 && pi[2] <= K) &&
                (pi[4] >= 0 && pi[4] <= K) && (pi[6] >= 0 && pi[6] <= K);
    return is64 ? pi[2 * b] : pi[b];
}
__device__ __forceinline__ float expc(float e) { return __expf(fminf(e, 80.0f)); }

// ---------------------------------------------------------------------------
__global__ void init_kernel(int b_count) {
    int i = blockIdx.x * blockDim.x + threadIdx.x;
    int nkv4 = b_count * 128 * 32;
    if (i < nkv4) ((float4*)g_kv)[i] = make_float4(0.f, 0.f, 0.f, 0.f);
    if (i < b_count * 32) ((float4*)g_ksum)[i] = make_float4(0.f, 0.f, 0.f, 0.f);
}

// ---------------------------------------------------------------------------
// kv_kernel: grid (K/512, B), 256 threads, 4 k-tiles per CTA.
// Tiles: T0/T1 proj bf16 hi/lo, T2/T3 X bf16 hi/lo, T4 V fp16, T5 S fp16.
// ---------------------------------------------------------------------------
__global__ void __launch_bounds__(256)
kv_kernel(const float* __restrict__ ks, const float* __restrict__ vs,
          const float* __restrict__ proj, const void* __restrict__ vl, int K) {
    extern __shared__ char smr[];
    float* hbuf = (float*)smr;                    // [128]
    char* tiles = smr + 2048;
    char *T0 = tiles,                *T1 = tiles + TILE_BYTES,
         *T2 = tiles + 2*TILE_BYTES, *T3 = tiles + 3*TILE_BYTES,
         *T4 = tiles + 4*TILE_BYTES, *T5 = tiles + 5*TILE_BYTES;
    uint32_t u0 = smem_u32(T0), u1 = smem_u32(T1), u2 = smem_u32(T2),
             u3 = smem_u32(T3), u4 = smem_u32(T4), u5 = smem_u32(T5);

    int tid = threadIdx.x, w = tid >> 5, lane = tid & 31;
    int b = blockIdx.y;
    int vlb = get_vl(vl, b, K);
    int r0 = 16 * w + (lane >> 2);                // fragment row (m)

    {   // proj (persists) + first ks tile
        float4 h0[8], h1[8];
        ldg_half(proj, h0, 0);  ldg_half(proj, h1, 1);
        st_half_bf16(h0, T0, T1, 1.0f, nullptr, 0);
        st_half_bf16(h1, T0, T1, 1.0f, nullptr, 1);
        const float* x0 = ks + ((long)b * K + blockIdx.x * 512) * 128;
        ldg_half(x0, h0, 0);  ldg_half(x0, h1, 1);
        st_half_bf16(h0, T2, T3, NORM, hbuf, 0);
        st_half_bf16(h1, T2, T3, NORM, hbuf, 1);
    }
    __syncthreads();

    float C2[16][4];
#pragma unroll
    for (int t = 0; t < 16; t++)
#pragma unroll
        for (int e = 0; e < 4; e++) C2[t][e] = 0.0f;
    float ksp0 = 0.0f, ksp1 = 0.0f;

    for (int it = 0; it < 4; it++) {
        int kt0 = (blockIdx.x * 4 + it) * 128;
        const float* vsrc = vs + ((long)b * K + kt0) * 128;

        float C1[16][4];
#pragma unroll
        for (int t = 0; t < 16; t++)
#pragma unroll
            for (int e = 0; e < 4; e++) C1[t][e] = 0.0f;

        {   // GEMM1 with V prefetch interleaved (32-reg halves)
            float4 vr[8];
            ldg_half(vsrc, vr, 0);
            gemm3p(C1, u0, u1, u2, u3, w, lane, 0, 4);
            st_half_f16(vr, T4, 1.0f, 0);
            ldg_half(vsrc, vr, 1);
            gemm3p(C1, u0, u1, u2, u3, w, lane, 4, 8);
            st_half_f16(vr, T4, 1.0f, 1);
        }

        // Epilogue: S^T[m][k] -> T5 (fp16), ksum accum.
#pragma unroll
        for (int t = 0; t < 16; t++) {
            int c0 = t * 8 + (lane & 3) * 2;
            float m0 = ((kt0 + c0)     < vlb) ? RSQ : 0.0f;
            float m1 = ((kt0 + c0 + 1) < vlb) ? RSQ : 0.0f;
            float h0 = hbuf[c0], h1 = hbuf[c0 + 1];
            float s00 = expc(C1[t][0] - h0) * m0;
            float s01 = expc(C1[t][1] - h1) * m1;
            float s10 = expc(C1[t][2] - h0) * m0;
            float s11 = expc(C1[t][3] - h1) * m1;
            ksp0 += s00 + s01;
            ksp1 += s10 + s11;
            uint32_t off0 = (uint32_t)(r0 * ROWB + c0 * 2);
            *(uint32_t*)(T5 + off0)            = f16x2(s00, s01);
            *(uint32_t*)(T5 + off0 + 8 * ROWB) = f16x2(s10, s11);
        }
        __syncthreads();                          // #1: S+V visible; X reads done

        // GEMM2 with next-X prefetch interleaved.
        bool pf = (it < 3);
        const float* xn = ks + ((long)b * K + kt0 + 128) * 128;
        {
            float4 kr[8];
            if (pf) ldg_half(xn, kr, 0);
            gemm1p(C2, u5, u4, w, lane, 0, 4);
            if (pf) { st_half_bf16(kr, T2, T3, NORM, hbuf, 0); ldg_half(xn, kr, 1); }
            gemm1p(C2, u5, u4, w, lane, 4, 8);
            if (pf) st_half_bf16(kr, T2, T3, NORM, hbuf, 1);
        }
        __syncthreads();                          // #2: GEMM2 + X(it+1) complete
    }

    float* kvb = g_kv + b * 128 * 128;
#pragma unroll
    for (int t = 0; t < 16; t++) {
        int v0 = t * 8 + (lane & 3) * 2;
        atomicAdd(kvb + r0 * 128 + v0,           C2[t][0]);
        atomicAdd(kvb + r0 * 128 + v0 + 1,       C2[t][1]);
        atomicAdd(kvb + (r0 + 8) * 128 + v0,     C2[t][2]);
        atomicAdd(kvb + (r0 + 8) * 128 + v0 + 1, C2[t][3]);
    }
    ksp0 += __shfl_xor_sync(0xFFFFFFFFu, ksp0, 1);
    ksp0 += __shfl_xor_sync(0xFFFFFFFFu, ksp0, 2);
    ksp1 += __shfl_xor_sync(0xFFFFFFFFu, ksp1, 1);
    ksp1 += __shfl_xor_sync(0xFFFFFFFFu, ksp1, 2);
    if ((lane & 3) == 0) {
        atomicAdd(&g_ksum[b * 128 + r0], ksp0);
        atomicAdd(&g_ksum[b * 128 + r0 + 8], ksp1);
    }
}

// ---------------------------------------------------------------------------
// out_kernel: grid (Q/512, B), 256 threads, 4 q-tiles per CTA.
// Tiles: T0/T1 proj bf16 hi/lo, T2/T3 Q bf16 hi/lo, T4 kv fp16 (x1/16), T5 Q' fp16.
// ---------------------------------------------------------------------------
__global__ void __launch_bounds__(256)
out_kernel(const float* __restrict__ qs, const float* __restrict__ proj,
           float* __restrict__ out, int Q) {
    extern __shared__ char smr[];
    float* hbuf   = (float*)smr;                  // [128]
    float* ksum_s = (float*)(smr + 512);          // [128]
    float* denb   = (float*)(smr + 1024);         // [128]
    char* tiles = smr + 2048;
    char *T0 = tiles,                *T1 = tiles + TILE_BYTES,
         *T2 = tiles + 2*TILE_BYTES, *T3 = tiles + 3*TILE_BYTES,
         *T4 = tiles + 4*TILE_BYTES, *T5 = tiles + 5*TILE_BYTES;
    uint32_t u0 = smem_u32(T0), u1 = smem_u32(T1), u2 = smem_u32(T2),
             u3 = smem_u32(T3), u4 = smem_u32(T4), u5 = smem_u32(T5);

    int tid = threadIdx.x, w = tid >> 5, lane = tid & 31;
    int b = blockIdx.y;
    int r0 = 16 * w + (lane >> 2);                // fragment row (q)

    {   // proj bf16 split, kv fp16 (scaled), ksum, first qs tile
        float4 h0[8], h1[8];
        ldg_half(proj, h0, 0);  ldg_half(proj, h1, 1);
        st_half_bf16(h0, T0, T1, 1.0f, nullptr, 0);
        st_half_bf16(h1, T0, T1, 1.0f, nullptr, 1);
        const float* kvb = g_kv + b * 128 * 128;
        ldg_half(kvb, h0, 0);  ldg_half(kvb, h1, 1);
        st_half_f16(h0, T4, KV_SCALE, 0);
        st_half_f16(h1, T4, KV_SCALE, 1);
        const float* q0p = qs + ((long)b * Q + blockIdx.x * 512) * 128;
        ldg_half(q0p, h0, 0);  ldg_half(q0p, h1, 1);
        st_half_bf16(h0, T2, T3, NORM, hbuf, 0);
        st_half_bf16(h1, T2, T3, NORM, hbuf, 1);
        if (tid < 128) ksum_s[tid] = g_ksum[b * 128 + tid];
    }
    __syncthreads();

    for (int it = 0; it < 4; it++) {
        int q0 = (blockIdx.x * 4 + it) * 128;

        float C1[16][4];
#pragma unroll
        for (int t = 0; t < 16; t++)
#pragma unroll
            for (int e = 0; e < 4; e++) C1[t][e] = 0.0f;
        gemm3p(C1, u2, u3, u0, u1, w, lane, 0, 8);    // P[q][m] = X . proj^T

        // Q'[q][m] (fp16) -> T5 ; den[q] = sum_m Q' * ksum[m].
        float hq0 = hbuf[r0], hq1 = hbuf[r0 + 8];
        float d0 = 0.0f, d1 = 0.0f;
#pragma unroll
        for (int t = 0; t < 16; t++) {
            int c0 = t * 8 + (lane & 3) * 2;
            float k0 = ksum_s[c0], k1 = ksum_s[c0 + 1];
            float s00 = expc(C1[t][0] - hq0) * RSQ;
            float s01 = expc(C1[t][1] - hq0) * RSQ;
            float s10 = expc(C1[t][2] - hq1) * RSQ;
            float s11 = expc(C1[t][3] - hq1) * RSQ;
            d0 += s00 * k0 + s01 * k1;
            d1 += s10 * k0 + s11 * k1;
            uint32_t off0 = (uint32_t)(r0 * ROWB + c0 * 2);
            *(uint32_t*)(T5 + off0)            = f16x2(s00, s01);
            *(uint32_t*)(T5 + off0 + 8 * ROWB) = f16x2(s10, s11);
        }
        d0 += __shfl_xor_sync(0xFFFFFFFFu, d0, 1);
        d0 += __shfl_xor_sync(0xFFFFFFFFu, d0, 2);
        d1 += __shfl_xor_sync(0xFFFFFFFFu, d1, 1);
        d1 += __shfl_xor_sync(0xFFFFFFFFu, d1, 2);
        if ((lane & 3) == 0) {
            denb[r0]     = (d0 < EPSD) ? EPSD : d0;
            denb[r0 + 8] = (d1 < EPSD) ? EPSD : d1;
        }
        __syncthreads();                          // #1: Q' + denb visible

        bool pf = (it < 3);
        const float* qn = qs + ((long)b * Q + q0 + 128) * 128;
        float C2[16][4];
#pragma unroll
        for (int t = 0; t < 16; t++)
#pragma unroll
            for (int e = 0; e < 4; e++) C2[t][e] = 0.0f;
        {
            float4 qr[8];
            if (pf) ldg_half(qn, qr, 0);
            gemm1p(C2, u5, u4, w, lane, 0, 4);
            if (pf) { st_half_bf16(qr, T2, T3, NORM, hbuf, 0); ldg_half(qn, qr, 1); }
            gemm1p(C2, u5, u4, w, lane, 4, 8);
            if (pf) st_half_bf16(qr, T2, T3, NORM, hbuf, 1);
        }

        float inv0 = KV_UNSCALE / denb[r0], inv1 = KV_UNSCALE / denb[r0 + 8];
        float* orow0 = out + ((long)b * Q + q0 + r0) * 128;
        float* orow1 = orow0 + 8 * 128;
#pragma unroll
        for (int t = 0; t < 16; t++) {
            int v0 = t * 8 + (lane & 3) * 2;
            *(float2*)(orow0 + v0) = make_float2(C2[t][0] * inv0, C2[t][1] * inv0);
            *(float2*)(orow1 + v0) = make_float2(C2[t][2] * inv1, C2[t][3] * inv1);
        }
        __syncthreads();                          // #2: GEMM2 + Q(it+1) complete
    }
}

// ---------------------------------------------------------------------------
extern "C" void kernel_launch(void* const* d_in, const int* in_sizes, int n_in,
                              void* d_out, int out_size) {
    const float* qs   = (const float*)d_in[0];
    const float* ks   = (const float*)d_in[1];
    const float* vs   = (const float*)d_in[2];
    const float* proj = (const float*)d_in[3];
    const void*  vl   = d_in[4];

    int B = in_sizes[4];
    if (B > MAX_B) B = MAX_B;
    int Q = in_sizes[0] / (B * 128);
    int K = in_sizes[1] / (B * 128);

    cudaFuncSetAttribute(kv_kernel,  cudaFuncAttributeMaxDynamicSharedMemorySize, SMEM_DYN);
    cudaFuncSetAttribute(out_kernel, cudaFuncAttributeMaxDynamicSharedMemorySize, SMEM_DYN);

    int n4 = B * 128 * 32;
    init_kernel<<<(n4 + 255) / 256, 256>>>(B);

    dim3 gkv(K / 512, B);
    kv_kernel<<<gkv, 256, SMEM_DYN>>>(ks, vs, proj, vl, K);

    dim3 gout(Q / 512, B);
    out_kernel<<<gout, 256, SMEM_DYN>>>(qs, proj, (float*)d_out, Q);
}